// round 2
// baseline (speedup 1.0000x reference)
#include <cuda_runtime.h>
#include <math.h>

// ---------------------------------------------------------------------------
// Problem constants
// ---------------------------------------------------------------------------
#define TT 64      // tgt time
#define BB 32      // batch
#define DD 512     // model dim
#define HH 8       // heads
#define HD 64      // head dim
#define SS 64      // semantics slots
#define MM 256     // memory length
#define FFD 2048   // ffn hidden
#define NTB (TT*BB)   // 2048 rows, row index r = t*32 + b
#define NMB (MM*BB)   // 8192 rows, row index r = m*32 + b

// ---------------------------------------------------------------------------
// Scratch (device globals; no allocation anywhere)
// ---------------------------------------------------------------------------
__device__ float g_fc  [NTB*DD];
__device__ float g_sc  [BB*SS*DD];
__device__ float g_relk[NTB*DD];
__device__ float g_qb  [NTB*DD];
__device__ float g_kb  [NMB*DD];
__device__ float g_vb  [NMB*DD];
__device__ float g_S   [BB*HH*TT*MM];   // scores, row stride MM (=256) always
__device__ float g_attn[NTB*DD];
__device__ float g_x1  [NTB*DD];
__device__ float g_x2  [NTB*DD];
__device__ float g_x3  [NTB*DD];
__device__ float g_tmp [NTB*DD];
__device__ float g_ffh [NTB*FFD];

// ---------------------------------------------------------------------------
// Generic GEMM: C[M,N] = act(A[M,K](lda) @ W[N,K](ldw)^T + bias + resid)
// 64x64 tile, BK=32, 256 threads, 4x4 micro-tile, K-major smem with pad 8.
// ---------------------------------------------------------------------------
__global__ void __launch_bounds__(256)
gemm_kernel(const float* __restrict__ A, int lda,
            const float* __restrict__ W, int ldw,
            const float* __restrict__ bias,
            const float* __restrict__ resid,
            float* __restrict__ C,
            int N, int K, int doRelu)
{
    __shared__ __align__(16) float As[32][72];
    __shared__ __align__(16) float Ws[32][72];
    const int tid = threadIdx.x;
    const int tx = tid & 15, ty = tid >> 4;
    const int row0 = blockIdx.y * 64, col0 = blockIdx.x * 64;

    const float* Ab = A + (long)row0 * lda;
    const float* Wb = W + (long)col0 * ldw;

    float acc[4][4];
#pragma unroll
    for (int i = 0; i < 4; i++)
#pragma unroll
        for (int j = 0; j < 4; j++) acc[i][j] = 0.f;

    for (int k0 = 0; k0 < K; k0 += 32) {
#pragma unroll
        for (int p = 0; p < 8; p++) {
            int idx = p * 256 + tid;
            int kl = idx & 31, r = idx >> 5;
            As[kl][r] = Ab[(long)r * lda + k0 + kl];
            Ws[kl][r] = Wb[(long)r * ldw + k0 + kl];
        }
        __syncthreads();
#pragma unroll
        for (int kk = 0; kk < 32; kk++) {
            float4 av4 = *(const float4*)&As[kk][ty * 4];
            float4 bv4 = *(const float4*)&Ws[kk][tx * 4];
            float av[4] = {av4.x, av4.y, av4.z, av4.w};
            float bv[4] = {bv4.x, bv4.y, bv4.z, bv4.w};
#pragma unroll
            for (int i = 0; i < 4; i++)
#pragma unroll
                for (int j = 0; j < 4; j++)
                    acc[i][j] += av[i] * bv[j];
        }
        __syncthreads();
    }

    const int cbase = col0 + tx * 4;
#pragma unroll
    for (int i = 0; i < 4; i++) {
        const int r = row0 + ty * 4 + i;
        float4 v = make_float4(acc[i][0], acc[i][1], acc[i][2], acc[i][3]);
        if (bias) {
            float4 bb = *(const float4*)&bias[cbase];
            v.x += bb.x; v.y += bb.y; v.z += bb.z; v.w += bb.w;
        }
        if (resid) {
            float4 rr = *(const float4*)&resid[(long)r * N + cbase];
            v.x += rr.x; v.y += rr.y; v.z += rr.z; v.w += rr.w;
        }
        if (doRelu) {
            v.x = fmaxf(v.x, 0.f); v.y = fmaxf(v.y, 0.f);
            v.z = fmaxf(v.z, 0.f); v.w = fmaxf(v.w, 0.f);
        }
        *(float4*)&C[(long)r * N + cbase] = v;
    }
}

// ---------------------------------------------------------------------------
// Fused relevance kernel: one CTA per (t,b) row r = t*32+b.
// For s in [0,64): h[s,:] = relu(fc[r,:]+b0 + sc[b,s,:]);
// score[s] = relu(h @ w1^T + b1) . w2 ; a = softmax(score);
// relk[r,:] = sum_s a[s] * sem[b,s,:].
// Per-CTA GEMM 64x512x512, j2 processed in 4 blocks of 128 (h2 never stored).
// ---------------------------------------------------------------------------
__global__ void __launch_bounds__(256)
relevance_kernel(const float* __restrict__ fc, const float* __restrict__ sc,
                 const float* __restrict__ sem, const float* __restrict__ b0,
                 const float* __restrict__ w1, const float* __restrict__ b1,
                 const float* __restrict__ w2, float* __restrict__ relk)
{
    __shared__ __align__(16) float fcb[DD];
    __shared__ __align__(16) float Hs[32][72];    // K-major: Hs[k][s]
    __shared__ __align__(16) float Ws[32][136];   // K-major: Ws[k][j2]
    __shared__ float scorebuf[SS];
    __shared__ float abuf[SS];
    __shared__ float red[2];

    const int r = blockIdx.x;       // t*32 + b
    const int b = r & 31;
    const int tid = threadIdx.x;
    const int tx = tid & 31, ty = tid >> 5;

    for (int i = tid; i < DD; i += 256) fcb[i] = fc[(long)r * DD + i] + b0[i];
    __syncthreads();

    float sacc[8];
#pragma unroll
    for (int i = 0; i < 8; i++) sacc[i] = 0.f;

    for (int j2b = 0; j2b < 4; j2b++) {
        float acc[8][4];
#pragma unroll
        for (int i = 0; i < 8; i++)
#pragma unroll
            for (int j = 0; j < 4; j++) acc[i][j] = 0.f;

        for (int k0 = 0; k0 < DD; k0 += 32) {
#pragma unroll
            for (int p = 0; p < 8; p++) {
                int idx = p * 256 + tid;
                int kl = idx & 31, s = idx >> 5;
                Hs[kl][s] = fmaxf(fcb[k0 + kl] + sc[((long)(b * SS + s)) * DD + k0 + kl], 0.f);
            }
#pragma unroll
            for (int p = 0; p < 16; p++) {
                int idx = p * 256 + tid;
                int kl = idx & 31, j2l = idx >> 5;
                Ws[kl][j2l] = w1[((long)(j2b * 128 + j2l)) * DD + k0 + kl];
            }
            __syncthreads();
#pragma unroll
            for (int kk = 0; kk < 32; kk++) {
                float4 a0 = *(const float4*)&Hs[kk][ty * 8];
                float4 a1 = *(const float4*)&Hs[kk][ty * 8 + 4];
                float4 bv4 = *(const float4*)&Ws[kk][tx * 4];
                float av[8] = {a0.x, a0.y, a0.z, a0.w, a1.x, a1.y, a1.z, a1.w};
                float bw[4] = {bv4.x, bv4.y, bv4.z, bv4.w};
#pragma unroll
                for (int i = 0; i < 8; i++)
#pragma unroll
                    for (int j = 0; j < 4; j++)
                        acc[i][j] += av[i] * bw[j];
            }
            __syncthreads();
        }
        // epilogue: relu(+b1) dot w2, reduce over 128-col block (32 lanes x 4)
        const int cb = j2b * 128 + tx * 4;
        float b1v[4], w2v[4];
#pragma unroll
        for (int j = 0; j < 4; j++) { b1v[j] = b1[cb + j]; w2v[j] = w2[cb + j]; }
#pragma unroll
        for (int i = 0; i < 8; i++) {
            float sp = 0.f;
#pragma unroll
            for (int j = 0; j < 4; j++)
                sp += fmaxf(acc[i][j] + b1v[j], 0.f) * w2v[j];
#pragma unroll
            for (int o = 16; o; o >>= 1)
                sp += __shfl_down_sync(0xffffffffu, sp, o);
            sacc[i] += sp;   // lane 0 meaningful
        }
    }
    if (tx == 0) {
#pragma unroll
        for (int i = 0; i < 8; i++) scorebuf[ty * 8 + i] = sacc[i];
    }
    __syncthreads();
    // softmax over 64 (b2 is shift-invariant -> dropped)
    if (tid == 0) {
        float m = -1e30f;
        for (int s = 0; s < SS; s++) m = fmaxf(m, scorebuf[s]);
        red[0] = m;
    }
    __syncthreads();
    if (tid < SS) abuf[tid] = expf(scorebuf[tid] - red[0]);
    __syncthreads();
    if (tid == 0) {
        float s = 0.f;
        for (int i = 0; i < SS; i++) s += abuf[i];
        red[1] = 1.f / s;
    }
    __syncthreads();
    const float inv = red[1];
    for (int d = tid; d < DD; d += 256) {
        float a = 0.f;
        for (int s = 0; s < SS; s++)
            a += abuf[s] * sem[((long)(b * SS + s)) * DD + d];
        relk[(long)r * DD + d] = a * inv;
    }
}

// ---------------------------------------------------------------------------
// Attention scores: S[bh, q, kt] = scale * qh[q,b,h,:] . kh[kt,b,h,:]
// One CTA per (b,h). Row buffers are (row = t*32+b, col = h*64+e).
// ---------------------------------------------------------------------------
__global__ void __launch_bounds__(256)
attn_scores_kernel(const float* __restrict__ q, const float* __restrict__ k,
                   float* __restrict__ S, int Tk)
{
    const int bh = blockIdx.x;
    const int b = bh >> 3, h = bh & 7;
    __shared__ __align__(16) float Qs[64][72];  // [q][e]
    __shared__ __align__(16) float Ks[64][72];  // K-major [e][kt]
    const int tid = threadIdx.x;
    const int tx = tid & 31, ty = tid >> 5;
    const float scale = 0.125f;   // 1/sqrt(64)

#pragma unroll
    for (int p = 0; p < 16; p++) {
        int idx = p * 256 + tid;
        int e = idx & 63, r = idx >> 6;
        Qs[r][e] = q[((long)(r * 32 + b)) * DD + h * 64 + e];
    }
    for (int kt0 = 0; kt0 < Tk; kt0 += 64) {
#pragma unroll
        for (int p = 0; p < 16; p++) {
            int idx = p * 256 + tid;
            int e = idx & 63, r = idx >> 6;
            Ks[e][r] = k[((long)((kt0 + r) * 32 + b)) * DD + h * 64 + e];
        }
        __syncthreads();
        float acc[8][2];
#pragma unroll
        for (int i = 0; i < 8; i++) { acc[i][0] = 0.f; acc[i][1] = 0.f; }
#pragma unroll 8
        for (int e = 0; e < 64; e++) {
            float b0v = Ks[e][tx * 2];
            float b1v = Ks[e][tx * 2 + 1];
#pragma unroll
            for (int i = 0; i < 8; i++) {
                float a = Qs[ty * 8 + i][e];
                acc[i][0] += a * b0v;
                acc[i][1] += a * b1v;
            }
        }
#pragma unroll
        for (int i = 0; i < 8; i++) {
            int qr = ty * 8 + i;
            float2 v = make_float2(acc[i][0] * scale, acc[i][1] * scale);
            *(float2*)&S[((long)(bh * 64 + qr)) * MM + kt0 + tx * 2] = v;
        }
        __syncthreads();
    }
}

// ---------------------------------------------------------------------------
// Row softmax over Tk elements (row stride 256); one warp per row.
// ---------------------------------------------------------------------------
__global__ void __launch_bounds__(256)
softmax_rows_kernel(float* __restrict__ S, int Tk)
{
    const int row = blockIdx.x * 8 + (threadIdx.x >> 5);
    const int lane = threadIdx.x & 31;
    float* p = S + (long)row * MM;
    const int n = Tk >> 5;   // 2 or 8
    float vals[8];
    float m = -1e30f;
    for (int c = 0; c < n; c++) { vals[c] = p[lane + c * 32]; m = fmaxf(m, vals[c]); }
#pragma unroll
    for (int o = 16; o; o >>= 1) m = fmaxf(m, __shfl_xor_sync(0xffffffffu, m, o));
    float s = 0.f;
    for (int c = 0; c < n; c++) { vals[c] = expf(vals[c] - m); s += vals[c]; }
#pragma unroll
    for (int o = 16; o; o >>= 1) s += __shfl_xor_sync(0xffffffffu, s, o);
    const float inv = 1.f / s;
    for (int c = 0; c < n; c++) p[lane + c * 32] = vals[c] * inv;
}

// ---------------------------------------------------------------------------
// O[q,b,h,:] = sum_kt P[bh,q,kt] * vh[kt,b,h,:]; one CTA per (b,h).
// ---------------------------------------------------------------------------
__global__ void __launch_bounds__(256)
attn_av_kernel(const float* __restrict__ P, const float* __restrict__ v,
               float* __restrict__ O, int Tk)
{
    const int bh = blockIdx.x;
    const int b = bh >> 3, h = bh & 7;
    __shared__ __align__(16) float Ps[64][72];  // [q][kt_local]
    __shared__ __align__(16) float Vs[64][72];  // [kt_local][e]
    const int tid = threadIdx.x;
    const int tx = tid & 31, ty = tid >> 5;

    float acc[8][2];
#pragma unroll
    for (int i = 0; i < 8; i++) { acc[i][0] = 0.f; acc[i][1] = 0.f; }

    for (int kt0 = 0; kt0 < Tk; kt0 += 64) {
#pragma unroll
        for (int p = 0; p < 16; p++) {
            int idx = p * 256 + tid;
            int kl = idx & 63, r = idx >> 6;
            Ps[r][kl] = P[((long)(bh * 64 + r)) * MM + kt0 + kl];
            Vs[r][kl] = v[((long)((kt0 + r) * 32 + b)) * DD + h * 64 + kl];
        }
        __syncthreads();
#pragma unroll 8
        for (int kk = 0; kk < 64; kk++) {
            float b0v = Vs[kk][tx * 2];
            float b1v = Vs[kk][tx * 2 + 1];
#pragma unroll
            for (int i = 0; i < 8; i++) {
                float a = Ps[ty * 8 + i][kk];
                acc[i][0] += a * b0v;
                acc[i][1] += a * b1v;
            }
        }
        __syncthreads();
    }
#pragma unroll
    for (int i = 0; i < 8; i++) {
        int qr = ty * 8 + i;
        float2 o = make_float2(acc[i][0], acc[i][1]);
        *(float2*)&O[((long)(qr * 32 + b)) * DD + h * 64 + tx * 2] = o;
    }
}

// ---------------------------------------------------------------------------
// LayerNorm over 512-wide rows; one warp per row; two-pass (mean then var).
// ---------------------------------------------------------------------------
__global__ void __launch_bounds__(256)
layernorm_kernel(const float* __restrict__ x, const float* __restrict__ g,
                 const float* __restrict__ bb, float* __restrict__ out)
{
    const int row = blockIdx.x * 8 + (threadIdx.x >> 5);
    const int lane = threadIdx.x & 31;
    const float* p = x + (long)row * DD;
    float v[16];
    float s = 0.f;
#pragma unroll
    for (int c = 0; c < 16; c++) { v[c] = p[lane + c * 32]; s += v[c]; }
#pragma unroll
    for (int o = 16; o; o >>= 1) s += __shfl_xor_sync(0xffffffffu, s, o);
    const float mu = s * (1.f / DD);
    float q = 0.f;
#pragma unroll
    for (int c = 0; c < 16; c++) { float d = v[c] - mu; q += d * d; }
#pragma unroll
    for (int o = 16; o; o >>= 1) q += __shfl_xor_sync(0xffffffffu, q, o);
    const float rstd = rsqrtf(q * (1.f / DD) + 1e-5f);
#pragma unroll
    for (int c = 0; c < 16; c++) {
        int col = lane + c * 32;
        out[(long)row * DD + col] = (v[c] - mu) * rstd * g[col] + bb[col];
    }
}

// ---------------------------------------------------------------------------
// Host side
// ---------------------------------------------------------------------------
static inline void run_gemm(const float* A, int lda, const float* W, int ldw,
                            const float* bias, const float* resid, float* C,
                            int M, int N, int K, int relu)
{
    dim3 grid(N / 64, M / 64);
    gemm_kernel<<<grid, 256>>>(A, lda, W, ldw, bias, resid, C, N, K, relu);
}

extern "C" void kernel_launch(void* const* d_in, const int* in_sizes, int n_in,
                              void* d_out, int out_size)
{
    const float* tgt      = (const float*)d_in[0];
    const float* memory   = (const float*)d_in[1];
    const float* sem      = (const float*)d_in[2];
    const float* pt_wqkv  = (const float*)d_in[3];
    const float* pt_bqkv  = (const float*)d_in[4];
    const float* pt_wo    = (const float*)d_in[5];
    const float* pt_bo    = (const float*)d_in[6];
    const float* sa_wqkv  = (const float*)d_in[7];
    const float* sa_bqkv  = (const float*)d_in[8];
    const float* sa_wo    = (const float*)d_in[9];
    const float* sa_bo    = (const float*)d_in[10];
    const float* ca_wqkv  = (const float*)d_in[11];
    const float* ca_bqkv  = (const float*)d_in[12];
    const float* ca_wo    = (const float*)d_in[13];
    const float* ca_bo    = (const float*)d_in[14];
    const float* mlp_w0   = (const float*)d_in[15];
    const float* mlp_b0   = (const float*)d_in[16];
    const float* mlp_w1   = (const float*)d_in[17];
    const float* mlp_b1   = (const float*)d_in[18];
    const float* mlp_w2   = (const float*)d_in[19];
    /* mlp_b2 (d_in[20]) is shift-invariant under softmax -> unused */
    const float* ffn_w1   = (const float*)d_in[21];
    const float* ffn_b1   = (const float*)d_in[22];
    const float* ffn_w2   = (const float*)d_in[23];
    const float* ffn_b2   = (const float*)d_in[24];
    const float* ln1_g    = (const float*)d_in[25];
    const float* ln1_b    = (const float*)d_in[26];
    const float* ln2_g    = (const float*)d_in[27];
    const float* ln2_b    = (const float*)d_in[28];
    const float* ln3_g    = (const float*)d_in[29];
    const float* ln3_b    = (const float*)d_in[30];
    float* out = (float*)d_out;

    float *fc, *sc, *relk, *qb, *kb, *vb, *Sb, *attn, *x1, *x2, *x3, *tmp, *ffh;
    cudaGetSymbolAddress((void**)&fc,   g_fc);
    cudaGetSymbolAddress((void**)&sc,   g_sc);
    cudaGetSymbolAddress((void**)&relk, g_relk);
    cudaGetSymbolAddress((void**)&qb,   g_qb);
    cudaGetSymbolAddress((void**)&kb,   g_kb);
    cudaGetSymbolAddress((void**)&vb,   g_vb);
    cudaGetSymbolAddress((void**)&Sb,   g_S);
    cudaGetSymbolAddress((void**)&attn, g_attn);
    cudaGetSymbolAddress((void**)&x1,   g_x1);
    cudaGetSymbolAddress((void**)&x2,   g_x2);
    cudaGetSymbolAddress((void**)&x3,   g_x3);
    cudaGetSymbolAddress((void**)&tmp,  g_tmp);
    cudaGetSymbolAddress((void**)&ffh,  g_ffh);

    // ---- relevant semantic -------------------------------------------------
    // fc[r=t*32+b, j] = tgt row . w0c[j,:]   (w0 is (512,1024); w0c cols 0..511)
    run_gemm(tgt, DD, mlp_w0,       2 * DD, nullptr, nullptr, fc, NTB, DD, DD, 0);
    // sc[b*64+s, j] = sem row . w0s[j,:]
    run_gemm(sem, DD, mlp_w0 + DD,  2 * DD, nullptr, nullptr, sc, BB * SS, DD, DD, 0);
    relevance_kernel<<<NTB, 256>>>(fc, sc, sem, mlp_b0, mlp_w1, mlp_b1, mlp_w2, relk);

    // ---- block 1: mha(tgt, sem_k, sem_k), residual, NO layernorm ----------
    run_gemm(tgt,  DD, pt_wqkv,              DD, pt_bqkv,        nullptr, qb, NTB, DD, DD, 0);
    run_gemm(relk, DD, pt_wqkv + DD * DD,    DD, pt_bqkv + DD,   nullptr, kb, NTB, DD, DD, 0);
    run_gemm(relk, DD, pt_wqkv + 2 * DD * DD, DD, pt_bqkv + 2 * DD, nullptr, vb, NTB, DD, DD, 0);
    attn_scores_kernel<<<BB * HH, 256>>>(qb, kb, Sb, TT);
    softmax_rows_kernel<<<BB * HH * TT / 8, 256>>>(Sb, TT);
    attn_av_kernel<<<BB * HH, 256>>>(Sb, vb, attn, TT);
    run_gemm(attn, DD, pt_wo, DD, pt_bo, tgt, x1, NTB, DD, DD, 0);

    // ---- block 2: self-attention + LN1 ------------------------------------
    run_gemm(x1, DD, sa_wqkv,              DD, sa_bqkv,        nullptr, qb, NTB, DD, DD, 0);
    run_gemm(x1, DD, sa_wqkv + DD * DD,    DD, sa_bqkv + DD,   nullptr, kb, NTB, DD, DD, 0);
    run_gemm(x1, DD, sa_wqkv + 2 * DD * DD, DD, sa_bqkv + 2 * DD, nullptr, vb, NTB, DD, DD, 0);
    attn_scores_kernel<<<BB * HH, 256>>>(qb, kb, Sb, TT);
    softmax_rows_kernel<<<BB * HH * TT / 8, 256>>>(Sb, TT);
    attn_av_kernel<<<BB * HH, 256>>>(Sb, vb, attn, TT);
    run_gemm(attn, DD, sa_wo, DD, sa_bo, x1, tmp, NTB, DD, DD, 0);
    layernorm_kernel<<<NTB / 8, 256>>>(tmp, ln1_g, ln1_b, x2);

    // ---- block 3: cross-attention over memory + LN2 ------------------------
    run_gemm(x2,     DD, ca_wqkv,              DD, ca_bqkv,        nullptr, qb, NTB, DD, DD, 0);
    run_gemm(memory, DD, ca_wqkv + DD * DD,    DD, ca_bqkv + DD,   nullptr, kb, NMB, DD, DD, 0);
    run_gemm(memory, DD, ca_wqkv + 2 * DD * DD, DD, ca_bqkv + 2 * DD, nullptr, vb, NMB, DD, DD, 0);
    attn_scores_kernel<<<BB * HH, 256>>>(qb, kb, Sb, MM);
    softmax_rows_kernel<<<BB * HH * TT / 8, 256>>>(Sb, MM);
    attn_av_kernel<<<BB * HH, 256>>>(Sb, vb, attn, MM);
    run_gemm(attn, DD, ca_wo, DD, ca_bo, x2, tmp, NTB, DD, DD, 0);
    layernorm_kernel<<<NTB / 8, 256>>>(tmp, ln2_g, ln2_b, x3);

    // ---- FFN + LN3 ---------------------------------------------------------
    run_gemm(x3,  DD,  ffn_w1, DD,  ffn_b1, nullptr, ffh, NTB, FFD, DD, 1);
    run_gemm(ffh, FFD, ffn_w2, FFD, ffn_b2, x3, tmp, NTB, DD, FFD, 0);
    layernorm_kernel<<<NTB / 8, 256>>>(tmp, ln3_g, ln3_b, out);
}

// round 5
// speedup vs baseline: 2.6317x; 2.6317x over previous
#include <cuda_runtime.h>
#include <math.h>

// ---------------------------------------------------------------------------
// Problem constants
// ---------------------------------------------------------------------------
#define TT 64
#define BB 32
#define DD 512
#define HH 8
#define HD 64
#define SS 64
#define MM 256
#define FFD 2048
#define NTB (TT*BB)   // 2048
#define NMB (MM*BB)   // 8192

// ---------------------------------------------------------------------------
// Scratch (device globals; no allocation anywhere)
// ---------------------------------------------------------------------------
__device__ float g_fc  [NTB*DD];
__device__ float g_sc  [BB*SS*DD];
__device__ float g_relk[NTB*DD];
__device__ float g_qb  [NTB*DD];
__device__ float g_qkv [NTB*3*DD];     // merged qkv (sa)
__device__ float g_kv  [NMB*2*DD];     // merged kv (pt uses NTB rows, ca uses NMB)
__device__ float g_S   [BB*HH*TT*MM];
__device__ float g_attn[NTB*DD];
__device__ float g_x1  [NTB*DD];
__device__ float g_x2  [NTB*DD];
__device__ float g_x3  [NTB*DD];
__device__ float g_tmp [NTB*DD];
__device__ float g_ffh [NTB*FFD];

// ---------------------------------------------------------------------------
// tf32 helpers
// ---------------------------------------------------------------------------
__device__ __forceinline__ unsigned f2t(float x) {
    unsigned u;
    asm("cvt.rna.tf32.f32 %0, %1;" : "=r"(u) : "f"(x));
    return u;
}
__device__ __forceinline__ void mma8(float* c, const unsigned* a, const unsigned* b) {
    asm volatile(
        "mma.sync.aligned.m16n8k8.row.col.f32.tf32.tf32.f32 "
        "{%0,%1,%2,%3}, {%4,%5,%6,%7}, {%8,%9}, {%0,%1,%2,%3};"
        : "+f"(c[0]), "+f"(c[1]), "+f"(c[2]), "+f"(c[3])
        : "r"(a[0]), "r"(a[1]), "r"(a[2]), "r"(a[3]), "r"(b[0]), "r"(b[1]));
}

// ---------------------------------------------------------------------------
// Tensor-core GEMM: C[M,N] = act(A[M,K](lda) @ W[N,K](ldw)^T + bias + resid)
// BM=128, BN=64, BK=32, 256 threads (8 warps as 4x2, warp tile 32x32).
// ---------------------------------------------------------------------------
#define GLDA 36
__global__ void __launch_bounds__(256)
gemm_tc(const float* __restrict__ A, int lda,
        const float* __restrict__ W, int ldw,
        const float* __restrict__ bias,
        const float* __restrict__ resid,
        float* __restrict__ C,
        int N, int K, int doRelu)
{
    __shared__ unsigned As[128 * GLDA];
    __shared__ unsigned Ws[64 * GLDA];
    const int tid = threadIdx.x;
    const int wid = tid >> 5, lane = tid & 31;
    const int g = lane >> 2, tig = lane & 3;
    const int wm = wid >> 1, wn = wid & 1;
    const int row0 = blockIdx.y * 128, col0 = blockIdx.x * 64;
    const float* Ab = A + (long)row0 * lda;
    const float* Wb = W + (long)col0 * ldw;

    float acc[2][4][4];
#pragma unroll
    for (int mt = 0; mt < 2; mt++)
#pragma unroll
        for (int nt = 0; nt < 4; nt++)
#pragma unroll
            for (int q = 0; q < 4; q++) acc[mt][nt][q] = 0.f;

    for (int k0 = 0; k0 < K; k0 += 32) {
#pragma unroll
        for (int p = 0; p < 4; p++) {
            int idx = p * 256 + tid;
            int r = idx >> 3, c4 = (idx & 7) * 4;
            float4 v = *(const float4*)(Ab + (long)r * lda + k0 + c4);
            unsigned* dst = &As[r * GLDA + c4];
            dst[0] = f2t(v.x); dst[1] = f2t(v.y); dst[2] = f2t(v.z); dst[3] = f2t(v.w);
        }
#pragma unroll
        for (int p = 0; p < 2; p++) {
            int idx = p * 256 + tid;
            int r = idx >> 3, c4 = (idx & 7) * 4;
            float4 v = *(const float4*)(Wb + (long)r * ldw + k0 + c4);
            unsigned* dst = &Ws[r * GLDA + c4];
            dst[0] = f2t(v.x); dst[1] = f2t(v.y); dst[2] = f2t(v.z); dst[3] = f2t(v.w);
        }
        __syncthreads();
#pragma unroll
        for (int kk = 0; kk < 4; kk++) {
            const int kb = kk * 8;
            unsigned a[2][4], b[4][2];
#pragma unroll
            for (int mt = 0; mt < 2; mt++) {
                int rb = wm * 32 + mt * 16;
                a[mt][0] = As[(rb + g) * GLDA + kb + tig];
                a[mt][1] = As[(rb + g + 8) * GLDA + kb + tig];
                a[mt][2] = As[(rb + g) * GLDA + kb + tig + 4];
                a[mt][3] = As[(rb + g + 8) * GLDA + kb + tig + 4];
            }
#pragma unroll
            for (int nt = 0; nt < 4; nt++) {
                int n = wn * 32 + nt * 8 + g;
                b[nt][0] = Ws[n * GLDA + kb + tig];
                b[nt][1] = Ws[n * GLDA + kb + tig + 4];
            }
#pragma unroll
            for (int mt = 0; mt < 2; mt++)
#pragma unroll
                for (int nt = 0; nt < 4; nt++)
                    mma8(acc[mt][nt], a[mt], b[nt]);
        }
        __syncthreads();
    }

#pragma unroll
    for (int mt = 0; mt < 2; mt++)
#pragma unroll
        for (int half = 0; half < 2; half++) {
            const int r = row0 + wm * 32 + mt * 16 + g + half * 8;
#pragma unroll
            for (int nt = 0; nt < 4; nt++) {
                const int c = col0 + wn * 32 + nt * 8 + 2 * tig;
                float v0 = acc[mt][nt][half * 2];
                float v1 = acc[mt][nt][half * 2 + 1];
                if (bias) { v0 += bias[c]; v1 += bias[c + 1]; }
                if (resid) {
                    float2 rr = *(const float2*)(resid + (long)r * N + c);
                    v0 += rr.x; v1 += rr.y;
                }
                if (doRelu) { v0 = fmaxf(v0, 0.f); v1 = fmaxf(v1, 0.f); }
                *(float2*)(C + (long)r * N + c) = make_float2(v0, v1);
            }
        }
}

// ---------------------------------------------------------------------------
// Fused relevance, tensor-core version. One CTA per (t-pair, b): 2 rows r.
// M-tile = 128 (2 rows x 64 s), N = 512 in 4 blocks of 128, K = 512.
// 8 warps as 4(M)x2(N), warp tile 32x64 (2 mtiles x 8 ntiles).
// ---------------------------------------------------------------------------
__global__ void __launch_bounds__(256, 1)
relevance_tc(const float* __restrict__ fc, const float* __restrict__ sc,
             const float* __restrict__ sem, const float* __restrict__ b0,
             const float* __restrict__ w1, const float* __restrict__ b1,
             const float* __restrict__ w2, float* __restrict__ relk)
{
    __shared__ float fcb[2][DD];
    __shared__ unsigned Hs[128 * GLDA];
    __shared__ unsigned Ws[128 * GLDA];
    __shared__ float spart[128][2];
    __shared__ float abuf[2][SS];

    const int bid = blockIdx.x;
    const int b = bid & 31;
    const int tp = bid >> 5;
    const int tid = threadIdx.x;
    const int wid = tid >> 5, lane = tid & 31;
    const int g = lane >> 2, tig = lane & 3;
    const int wm = wid & 3, wn = wid >> 2;

#pragma unroll
    for (int p = 0; p < 4; p++) {
        int idx = p * 256 + tid;
        int i = idx >> 9, d = idx & 511;
        fcb[i][d] = fc[((long)((2 * tp + i) * 32 + b)) * DD + d] + b0[d];
    }
    __syncthreads();

    float pacc[2][2];
    pacc[0][0] = pacc[0][1] = pacc[1][0] = pacc[1][1] = 0.f;

    for (int j2b = 0; j2b < 4; j2b++) {
        float acc[2][8][4];
#pragma unroll
        for (int mt = 0; mt < 2; mt++)
#pragma unroll
            for (int nt = 0; nt < 8; nt++)
#pragma unroll
                for (int q = 0; q < 4; q++) acc[mt][nt][q] = 0.f;

        for (int k0 = 0; k0 < DD; k0 += 32) {
            // build H tile (relu(fc + sc)) -> tf32
#pragma unroll
            for (int p = 0; p < 4; p++) {
                int idx = p * 256 + tid;
                int rr = idx >> 3, c4 = (idx & 7) * 4;
                int i = rr >> 6, s = rr & 63;
                float4 sv = *(const float4*)(sc + ((long)(b * SS + s)) * DD + k0 + c4);
                float4 fv = *(const float4*)(&fcb[i][k0 + c4]);
                unsigned* dst = &Hs[rr * GLDA + c4];
                dst[0] = f2t(fmaxf(sv.x + fv.x, 0.f));
                dst[1] = f2t(fmaxf(sv.y + fv.y, 0.f));
                dst[2] = f2t(fmaxf(sv.z + fv.z, 0.f));
                dst[3] = f2t(fmaxf(sv.w + fv.w, 0.f));
            }
            // load W1 tile
#pragma unroll
            for (int p = 0; p < 4; p++) {
                int idx = p * 256 + tid;
                int rr = idx >> 3, c4 = (idx & 7) * 4;
                float4 wv = *(const float4*)(w1 + ((long)(j2b * 128 + rr)) * DD + k0 + c4);
                unsigned* dst = &Ws[rr * GLDA + c4];
                dst[0] = f2t(wv.x); dst[1] = f2t(wv.y); dst[2] = f2t(wv.z); dst[3] = f2t(wv.w);
            }
            __syncthreads();
#pragma unroll
            for (int kk = 0; kk < 4; kk++) {
                const int kb = kk * 8;
                unsigned a[2][4], bfr[8][2];
#pragma unroll
                for (int mt = 0; mt < 2; mt++) {
                    int rb = wm * 32 + mt * 16;
                    a[mt][0] = Hs[(rb + g) * GLDA + kb + tig];
                    a[mt][1] = Hs[(rb + g + 8) * GLDA + kb + tig];
                    a[mt][2] = Hs[(rb + g) * GLDA + kb + tig + 4];
                    a[mt][3] = Hs[(rb + g + 8) * GLDA + kb + tig + 4];
                }
#pragma unroll
                for (int nt = 0; nt < 8; nt++) {
                    int n = wn * 64 + nt * 8 + g;
                    bfr[nt][0] = Ws[n * GLDA + kb + tig];
                    bfr[nt][1] = Ws[n * GLDA + kb + tig + 4];
                }
#pragma unroll
                for (int mt = 0; mt < 2; mt++)
#pragma unroll
                    for (int nt = 0; nt < 8; nt++)
                        mma8(acc[mt][nt], a[mt], bfr[nt]);
            }
            __syncthreads();
        }
        // epilogue: relu(+b1) . w2 over this 128-col block
#pragma unroll
        for (int mt = 0; mt < 2; mt++)
#pragma unroll
            for (int half = 0; half < 2; half++) {
                float acc_s = 0.f;
#pragma unroll
                for (int nt = 0; nt < 8; nt++) {
                    int c = j2b * 128 + wn * 64 + nt * 8 + 2 * tig;
                    float2 b1v = *(const float2*)(b1 + c);
                    float2 w2v = *(const float2*)(w2 + c);
                    acc_s += fmaxf(acc[mt][nt][half * 2] + b1v.x, 0.f) * w2v.x;
                    acc_s += fmaxf(acc[mt][nt][half * 2 + 1] + b1v.y, 0.f) * w2v.y;
                }
                pacc[mt][half] += acc_s;
            }
    }

    // reduce partial scores: within tig group of 4, then across the 2 N-warps
#pragma unroll
    for (int mt = 0; mt < 2; mt++)
#pragma unroll
        for (int half = 0; half < 2; half++) {
            float v = pacc[mt][half];
            v += __shfl_down_sync(0xffffffffu, v, 2);
            v += __shfl_down_sync(0xffffffffu, v, 1);
            if (tig == 0)
                spart[wm * 32 + mt * 16 + g + half * 8][wn] = v;
        }
    __syncthreads();

    __shared__ float scorebuf[2][SS];
    if (tid < 128) {
        float s = spart[tid][0] + spart[tid][1];
        scorebuf[tid >> 6][tid & 63] = s;
    }
    __syncthreads();

    // softmax over 64 per row i (warps 0,1)
    if (wid < 2) {
        int i = wid;
        float v0 = scorebuf[i][lane], v1 = scorebuf[i][lane + 32];
        float m = fmaxf(v0, v1);
#pragma unroll
        for (int o = 16; o; o >>= 1) m = fmaxf(m, __shfl_xor_sync(0xffffffffu, m, o));
        float e0 = expf(v0 - m), e1 = expf(v1 - m);
        float ssum = e0 + e1;
#pragma unroll
        for (int o = 16; o; o >>= 1) ssum += __shfl_xor_sync(0xffffffffu, ssum, o);
        float inv = 1.f / ssum;
        abuf[i][lane] = e0 * inv;
        abuf[i][lane + 32] = e1 * inv;
    }
    __syncthreads();

    // weighted sum of semantics
#pragma unroll
    for (int p = 0; p < 4; p++) {
        int idx = p * 256 + tid;
        int i = idx >> 9, d = idx & 511;
        float a = 0.f;
#pragma unroll 4
        for (int s = 0; s < SS; s++)
            a += abuf[i][s] * sem[((long)(b * SS + s)) * DD + d];
        relk[((long)((2 * tp + i) * 32 + b)) * DD + d] = a;
    }
}

// ---------------------------------------------------------------------------
// Attention scores: S[bh, q, kt] = scale * qh . kh ; one CTA per (b,h).
// ---------------------------------------------------------------------------
__global__ void __launch_bounds__(256)
attn_scores_kernel(const float* __restrict__ q, int ldq,
                   const float* __restrict__ k, int ldk,
                   float* __restrict__ S, int Tk)
{
    const int bh = blockIdx.x;
    const int b = bh >> 3, h = bh & 7;
    __shared__ __align__(16) float Qs[64][72];
    __shared__ __align__(16) float Ks[64][72];
    const int tid = threadIdx.x;
    const int tx = tid & 31, ty = tid >> 5;
    const float scale = 0.125f;

#pragma unroll
    for (int p = 0; p < 16; p++) {
        int idx = p * 256 + tid;
        int e = idx & 63, r = idx >> 6;
        Qs[r][e] = q[((long)(r * 32 + b)) * ldq + h * 64 + e];
    }
    for (int kt0 = 0; kt0 < Tk; kt0 += 64) {
#pragma unroll
        for (int p = 0; p < 16; p++) {
            int idx = p * 256 + tid;
            int e = idx & 63, r = idx >> 6;
            Ks[e][r] = k[((long)((kt0 + r) * 32 + b)) * ldk + h * 64 + e];
        }
        __syncthreads();
        float acc[8][2];
#pragma unroll
        for (int i = 0; i < 8; i++) { acc[i][0] = 0.f; acc[i][1] = 0.f; }
#pragma unroll 8
        for (int e = 0; e < 64; e++) {
            float b0v = Ks[e][tx * 2];
            float b1v = Ks[e][tx * 2 + 1];
#pragma unroll
            for (int i = 0; i < 8; i++) {
                float a = Qs[ty * 8 + i][e];
                acc[i][0] += a * b0v;
                acc[i][1] += a * b1v;
            }
        }
#pragma unroll
        for (int i = 0; i < 8; i++) {
            int qr = ty * 8 + i;
            float2 v = make_float2(acc[i][0] * scale, acc[i][1] * scale);
            *(float2*)&S[((long)(bh * 64 + qr)) * MM + kt0 + tx * 2] = v;
        }
        __syncthreads();
    }
}

__global__ void __launch_bounds__(256)
softmax_rows_kernel(float* __restrict__ S, int Tk)
{
    const int row = blockIdx.x * 8 + (threadIdx.x >> 5);
    const int lane = threadIdx.x & 31;
    float* p = S + (long)row * MM;
    const int n = Tk >> 5;
    float vals[8];
    float m = -1e30f;
    for (int c = 0; c < n; c++) { vals[c] = p[lane + c * 32]; m = fmaxf(m, vals[c]); }
#pragma unroll
    for (int o = 16; o; o >>= 1) m = fmaxf(m, __shfl_xor_sync(0xffffffffu, m, o));
    float s = 0.f;
    for (int c = 0; c < n; c++) { vals[c] = expf(vals[c] - m); s += vals[c]; }
#pragma unroll
    for (int o = 16; o; o >>= 1) s += __shfl_xor_sync(0xffffffffu, s, o);
    const float inv = 1.f / s;
    for (int c = 0; c < n; c++) p[lane + c * 32] = vals[c] * inv;
}

__global__ void __launch_bounds__(256)
attn_av_kernel(const float* __restrict__ P, const float* __restrict__ v, int ldv,
               float* __restrict__ O, int Tk)
{
    const int bh = blockIdx.x;
    const int b = bh >> 3, h = bh & 7;
    __shared__ __align__(16) float Ps[64][72];
    __shared__ __align__(16) float Vs[64][72];
    const int tid = threadIdx.x;
    const int tx = tid & 31, ty = tid >> 5;

    float acc[8][2];
#pragma unroll
    for (int i = 0; i < 8; i++) { acc[i][0] = 0.f; acc[i][1] = 0.f; }

    for (int kt0 = 0; kt0 < Tk; kt0 += 64) {
#pragma unroll
        for (int p = 0; p < 16; p++) {
            int idx = p * 256 + tid;
            int kl = idx & 63, r = idx >> 6;
            Ps[r][kl] = P[((long)(bh * 64 + r)) * MM + kt0 + kl];
            Vs[r][kl] = v[((long)((kt0 + r) * 32 + b)) * ldv + h * 64 + kl];
        }
        __syncthreads();
#pragma unroll 8
        for (int kk = 0; kk < 64; kk++) {
            float b0v = Vs[kk][tx * 2];
            float b1v = Vs[kk][tx * 2 + 1];
#pragma unroll
            for (int i = 0; i < 8; i++) {
                float a = Ps[ty * 8 + i][kk];
                acc[i][0] += a * b0v;
                acc[i][1] += a * b1v;
            }
        }
        __syncthreads();
    }
#pragma unroll
    for (int i = 0; i < 8; i++) {
        int qr = ty * 8 + i;
        float2 o = make_float2(acc[i][0], acc[i][1]);
        *(float2*)&O[((long)(qr * 32 + b)) * DD + h * 64 + tx * 2] = o;
    }
}

__global__ void __launch_bounds__(256)
layernorm_kernel(const float* __restrict__ x, const float* __restrict__ g,
                 const float* __restrict__ bb, float* __restrict__ out)
{
    const int row = blockIdx.x * 8 + (threadIdx.x >> 5);
    const int lane = threadIdx.x & 31;
    const float* p = x + (long)row * DD;
    float v[16];
    float s = 0.f;
#pragma unroll
    for (int c = 0; c < 16; c++) { v[c] = p[lane + c * 32]; s += v[c]; }
#pragma unroll
    for (int o = 16; o; o >>= 1) s += __shfl_xor_sync(0xffffffffu, s, o);
    const float mu = s * (1.f / DD);
    float q = 0.f;
#pragma unroll
    for (int c = 0; c < 16; c++) { float d = v[c] - mu; q += d * d; }
#pragma unroll
    for (int o = 16; o; o >>= 1) q += __shfl_xor_sync(0xffffffffu, q, o);
    const float rstd = rsqrtf(q * (1.f / DD) + 1e-5f);
#pragma unroll
    for (int c = 0; c < 16; c++) {
        int col = lane + c * 32;
        out[(long)row * DD + col] = (v[c] - mu) * rstd * g[col] + bb[col];
    }
}

// ---------------------------------------------------------------------------
// Host side
// ---------------------------------------------------------------------------
static inline void run_gemm(const float* A, int lda, const float* W, int ldw,
                            const float* bias, const float* resid, float* C,
                            int M, int N, int K, int relu)
{
    dim3 grid(N / 64, M / 128);
    gemm_tc<<<grid, 256>>>(A, lda, W, ldw, bias, resid, C, N, K, relu);
}

extern "C" void kernel_launch(void* const* d_in, const int* in_sizes, int n_in,
                              void* d_out, int out_size)
{
    const float* tgt      = (const float*)d_in[0];
    const float* memory   = (const float*)d_in[1];
    const float* sem      = (const float*)d_in[2];
    const float* pt_wqkv  = (const float*)d_in[3];
    const float* pt_bqkv  = (const float*)d_in[4];
    const float* pt_wo    = (const float*)d_in[5];
    const float* pt_bo    = (const float*)d_in[6];
    const float* sa_wqkv  = (const float*)d_in[7];
    const float* sa_bqkv  = (const float*)d_in[8];
    const float* sa_wo    = (const float*)d_in[9];
    const float* sa_bo    = (const float*)d_in[10];
    const float* ca_wqkv  = (const float*)d_in[11];
    const float* ca_bqkv  = (const float*)d_in[12];
    const float* ca_wo    = (const float*)d_in[13];
    const float* ca_bo    = (const float*)d_in[14];
    const float* mlp_w0   = (const float*)d_in[15];
    const float* mlp_b0   = (const float*)d_in[16];
    const float* mlp_w1   = (const float*)d_in[17];
    const float* mlp_b1   = (const float*)d_in[18];
    const float* mlp_w2   = (const float*)d_in[19];
    /* mlp_b2 shift-invariant under softmax -> unused */
    const float* ffn_w1   = (const float*)d_in[21];
    const float* ffn_b1   = (const float*)d_in[22];
    const float* ffn_w2   = (const float*)d_in[23];
    const float* ffn_b2   = (const float*)d_in[24];
    const float* ln1_g    = (const float*)d_in[25];
    const float* ln1_b    = (const float*)d_in[26];
    const float* ln2_g    = (const float*)d_in[27];
    const float* ln2_b    = (const float*)d_in[28];
    const float* ln3_g    = (const float*)d_in[29];
    const float* ln3_b    = (const float*)d_in[30];
    float* out = (float*)d_out;

    float *fc, *sc, *relk, *qb, *qkv, *kv, *Sb, *attn, *x1, *x2, *x3, *tmp, *ffh;
    cudaGetSymbolAddress((void**)&fc,   g_fc);
    cudaGetSymbolAddress((void**)&sc,   g_sc);
    cudaGetSymbolAddress((void**)&relk, g_relk);
    cudaGetSymbolAddress((void**)&qb,   g_qb);
    cudaGetSymbolAddress((void**)&qkv,  g_qkv);
    cudaGetSymbolAddress((void**)&kv,   g_kv);
    cudaGetSymbolAddress((void**)&Sb,   g_S);
    cudaGetSymbolAddress((void**)&attn, g_attn);
    cudaGetSymbolAddress((void**)&x1,   g_x1);
    cudaGetSymbolAddress((void**)&x2,   g_x2);
    cudaGetSymbolAddress((void**)&x3,   g_x3);
    cudaGetSymbolAddress((void**)&tmp,  g_tmp);
    cudaGetSymbolAddress((void**)&ffh,  g_ffh);

    // ---- relevant semantic -------------------------------------------------
    run_gemm(tgt, DD, mlp_w0,      2 * DD, nullptr, nullptr, fc, NTB,     DD, DD, 0);
    run_gemm(sem, DD, mlp_w0 + DD, 2 * DD, nullptr, nullptr, sc, BB * SS, DD, DD, 0);
    relevance_tc<<<NTB / 2, 256>>>(fc, sc, sem, mlp_b0, mlp_w1, mlp_b1, mlp_w2, relk);

    // ---- block 1: mha(tgt, sem_k, sem_k) + residual (no LN) ---------------
    run_gemm(tgt,  DD, pt_wqkv,           DD, pt_bqkv,      nullptr, qb, NTB, DD,     DD, 0);
    run_gemm(relk, DD, pt_wqkv + DD * DD, DD, pt_bqkv + DD, nullptr, kv, NTB, 2 * DD, DD, 0);
    attn_scores_kernel<<<BB * HH, 256>>>(qb, DD, kv, 2 * DD, Sb, TT);
    softmax_rows_kernel<<<BB * HH * TT / 8, 256>>>(Sb, TT);
    attn_av_kernel<<<BB * HH, 256>>>(Sb, kv + DD, 2 * DD, attn, TT);
    run_gemm(attn, DD, pt_wo, DD, pt_bo, tgt, x1, NTB, DD, DD, 0);

    // ---- block 2: self-attention + LN1 ------------------------------------
    run_gemm(x1, DD, sa_wqkv, DD, sa_bqkv, nullptr, qkv, NTB, 3 * DD, DD, 0);
    attn_scores_kernel<<<BB * HH, 256>>>(qkv, 3 * DD, qkv + DD, 3 * DD, Sb, TT);
    softmax_rows_kernel<<<BB * HH * TT / 8, 256>>>(Sb, TT);
    attn_av_kernel<<<BB * HH, 256>>>(Sb, qkv + 2 * DD, 3 * DD, attn, TT);
    run_gemm(attn, DD, sa_wo, DD, sa_bo, x1, tmp, NTB, DD, DD, 0);
    layernorm_kernel<<<NTB / 8, 256>>>(tmp, ln1_g, ln1_b, x2);

    // ---- block 3: cross-attention over memory + LN2 ------------------------
    run_gemm(x2,     DD, ca_wqkv,           DD, ca_bqkv,      nullptr, qb, NTB, DD,     DD, 0);
    run_gemm(memory, DD, ca_wqkv + DD * DD, DD, ca_bqkv + DD, nullptr, kv, NMB, 2 * DD, DD, 0);
    attn_scores_kernel<<<BB * HH, 256>>>(qb, DD, kv, 2 * DD, Sb, MM);
    softmax_rows_kernel<<<BB * HH * TT / 8, 256>>>(Sb, MM);
    attn_av_kernel<<<BB * HH, 256>>>(Sb, kv + DD, 2 * DD, attn, MM);
    run_gemm(attn, DD, ca_wo, DD, ca_bo, x2, tmp, NTB, DD, DD, 0);
    layernorm_kernel<<<NTB / 8, 256>>>(tmp, ln2_g, ln2_b, x3);

    // ---- FFN + LN3 ---------------------------------------------------------
    run_gemm(x3,  DD,  ffn_w1, DD,  ffn_b1, nullptr, ffh, NTB, FFD, DD,  1);
    run_gemm(ffh, FFD, ffn_w2, FFD, ffn_b2, x3,      tmp, NTB, DD,  FFD, 0);
    layernorm_kernel<<<NTB / 8, 256>>>(tmp, ln3_g, ln3_b, out);
}

// round 7
// speedup vs baseline: 3.2393x; 1.2309x over previous
#include <cuda_runtime.h>
#include <math.h>

// ---------------------------------------------------------------------------
// Problem constants
// ---------------------------------------------------------------------------
#define TT 64
#define BB 32
#define DD 512
#define HH 8
#define HD 64
#define SS 64
#define MM 256
#define FFD 2048
#define NTB (TT*BB)   // 2048
#define NMB (MM*BB)   // 8192

// ---------------------------------------------------------------------------
// Scratch (device globals; no allocation anywhere)
// ---------------------------------------------------------------------------
__device__ float g_fc  [NTB*DD];
__device__ float g_sc  [BB*SS*DD];
__device__ float g_relk[NTB*DD];
__device__ float g_qb  [NTB*DD];
__device__ float g_qkv [NTB*3*DD];
__device__ float g_kv  [NMB*2*DD];
__device__ float g_S   [BB*HH*TT*MM];
__device__ float g_attn[NTB*DD];
__device__ float g_x1  [NTB*DD];
__device__ float g_x2  [NTB*DD];
__device__ float g_x3  [NTB*DD];
__device__ float g_tmp [NTB*DD];
__device__ float g_ffh [NTB*FFD];

// ---------------------------------------------------------------------------
// tf32 helpers
// ---------------------------------------------------------------------------
__device__ __forceinline__ unsigned f2t(float x) {
    unsigned u;
    asm("cvt.rna.tf32.f32 %0, %1;" : "=r"(u) : "f"(x));
    return u;
}
__device__ __forceinline__ void mma8(float* c, const unsigned* a, const unsigned* b) {
    asm volatile(
        "mma.sync.aligned.m16n8k8.row.col.f32.tf32.tf32.f32 "
        "{%0,%1,%2,%3}, {%4,%5,%6,%7}, {%8,%9}, {%0,%1,%2,%3};"
        : "+f"(c[0]), "+f"(c[1]), "+f"(c[2]), "+f"(c[3])
        : "r"(a[0]), "r"(a[1]), "r"(a[2]), "r"(a[3]), "r"(b[0]), "r"(b[1]));
}
// XOR swizzle: row stride 32 words, k-group permuted by row -> conflict-free
// fragment LDS and 4-phase-floor uint4 STS.
__device__ __forceinline__ int swz(int row, int k) {
    return (row << 5) + (k ^ ((row & 7) << 2));
}

// ---------------------------------------------------------------------------
// Tensor-core GEMM: C[M,N] = act(A[M,K](lda) @ W[N,K](ldw)^T + bias + resid)
// BM=64, BN=64, BK=32, 128 threads (4 warps as 2x2, warp tile 32x32).
// Register-prefetch software pipeline; XOR-swizzled smem.
// ---------------------------------------------------------------------------
__global__ void __launch_bounds__(128)
gemm_tc(const float* __restrict__ A, int lda,
        const float* __restrict__ W, int ldw,
        const float* __restrict__ bias,
        const float* __restrict__ resid,
        float* __restrict__ C,
        int N, int K, int doRelu)
{
    __shared__ unsigned As[64 * 32];
    __shared__ unsigned Ws[64 * 32];
    const int tid = threadIdx.x;
    const int wid = tid >> 5, lane = tid & 31;
    const int g = lane >> 2, tig = lane & 3;
    const int wm = wid >> 1, wn = wid & 1;
    const int row0 = blockIdx.y * 64, col0 = blockIdx.x * 64;
    const float* Ab = A + (long)row0 * lda;
    const float* Wb = W + (long)col0 * ldw;
    const int lr = tid >> 3;            // load row (0..15 step per p adds 16)
    const int lc4 = (tid & 7) << 2;     // load col (float4)
    const int nk = K >> 5;

    float4 pa[4], pw[4];
#pragma unroll
    for (int p = 0; p < 4; p++) {
        int r = lr + p * 16;
        pa[p] = *(const float4*)(Ab + (long)r * lda + lc4);
        pw[p] = *(const float4*)(Wb + (long)r * ldw + lc4);
    }

    float acc[2][4][4];
#pragma unroll
    for (int mt = 0; mt < 2; mt++)
#pragma unroll
        for (int nt = 0; nt < 4; nt++)
#pragma unroll
            for (int q = 0; q < 4; q++) acc[mt][nt][q] = 0.f;

    for (int kc = 0; kc < nk; kc++) {
#pragma unroll
        for (int p = 0; p < 4; p++) {
            int r = lr + p * 16;
            *(uint4*)&As[swz(r, lc4)] =
                make_uint4(f2t(pa[p].x), f2t(pa[p].y), f2t(pa[p].z), f2t(pa[p].w));
            *(uint4*)&Ws[swz(r, lc4)] =
                make_uint4(f2t(pw[p].x), f2t(pw[p].y), f2t(pw[p].z), f2t(pw[p].w));
        }
        __syncthreads();
        if (kc + 1 < nk) {
            const int k0 = (kc + 1) << 5;
#pragma unroll
            for (int p = 0; p < 4; p++) {
                int r = lr + p * 16;
                pa[p] = *(const float4*)(Ab + (long)r * lda + k0 + lc4);
                pw[p] = *(const float4*)(Wb + (long)r * ldw + k0 + lc4);
            }
        }
#pragma unroll
        for (int kk = 0; kk < 4; kk++) {
            const int kb = kk * 8;
            unsigned a[2][4], b[4][2];
#pragma unroll
            for (int mt = 0; mt < 2; mt++) {
                int rb = wm * 32 + mt * 16;
                a[mt][0] = As[swz(rb + g,     kb + tig)];
                a[mt][1] = As[swz(rb + g + 8, kb + tig)];
                a[mt][2] = As[swz(rb + g,     kb + tig + 4)];
                a[mt][3] = As[swz(rb + g + 8, kb + tig + 4)];
            }
#pragma unroll
            for (int nt = 0; nt < 4; nt++) {
                int n = wn * 32 + nt * 8 + g;
                b[nt][0] = Ws[swz(n, kb + tig)];
                b[nt][1] = Ws[swz(n, kb + tig + 4)];
            }
#pragma unroll
            for (int mt = 0; mt < 2; mt++)
#pragma unroll
                for (int nt = 0; nt < 4; nt++)
                    mma8(acc[mt][nt], a[mt], b[nt]);
        }
        __syncthreads();
    }

#pragma unroll
    for (int mt = 0; mt < 2; mt++)
#pragma unroll
        for (int half = 0; half < 2; half++) {
            const int r = row0 + wm * 32 + mt * 16 + g + half * 8;
#pragma unroll
            for (int nt = 0; nt < 4; nt++) {
                const int c = col0 + wn * 32 + nt * 8 + 2 * tig;
                float v0 = acc[mt][nt][half * 2];
                float v1 = acc[mt][nt][half * 2 + 1];
                if (bias) { v0 += bias[c]; v1 += bias[c + 1]; }
                if (resid) {
                    float2 rr = *(const float2*)(resid + (long)r * N + c);
                    v0 += rr.x; v1 += rr.y;
                }
                if (doRelu) { v0 = fmaxf(v0, 0.f); v1 = fmaxf(v1, 0.f); }
                *(float2*)(C + (long)r * N + c) = make_float2(v0, v1);
            }
        }
}

// ---------------------------------------------------------------------------
// Fused relevance, tensor-core + pipelined. One CTA per (t-pair, b).
// M-tile = 128 (2 rows x 64 s), N = 512 in 4 blocks of 128, K = 512.
// 8 warps as 4(M)x2(N), warp tile 32x64.
// ---------------------------------------------------------------------------
__global__ void __launch_bounds__(256)
relevance_tc(const float* __restrict__ fc, const float* __restrict__ sc,
             const float* __restrict__ sem, const float* __restrict__ b0,
             const float* __restrict__ w1, const float* __restrict__ b1,
             const float* __restrict__ w2, float* __restrict__ relk)
{
    __shared__ float fcb[2][DD];
    __shared__ unsigned Hs[128 * 32];
    __shared__ unsigned Ws[128 * 32];
    __shared__ float spart[128][2];
    __shared__ float abuf[2][SS];
    __shared__ float scorebuf[2][SS];

    const int bid = blockIdx.x;
    const int b = bid & 31;
    const int tp = bid >> 5;
    const int tid = threadIdx.x;
    const int wid = tid >> 5, lane = tid & 31;
    const int g = lane >> 2, tig = lane & 3;
    const int wm = wid & 3, wn = wid >> 2;
    const int lr = tid >> 3;            // 0..31; +32*p
    const int lc4 = (tid & 7) << 2;
    const int ls = lr & 63;             // not used directly; see loop

#pragma unroll
    for (int p = 0; p < 4; p++) {
        int idx = p * 256 + tid;
        int i = idx >> 9, d = idx & 511;
        fcb[i][d] = fc[((long)((2 * tp + i) * 32 + b)) * DD + d] + b0[d];
    }
    __syncthreads();
    (void)ls;

    float pacc[2][2];
    pacc[0][0] = pacc[0][1] = pacc[1][0] = pacc[1][1] = 0.f;

    // prefetch (j2b=0, k0=0)
    float4 sv[4], wv[4];
#pragma unroll
    for (int p = 0; p < 4; p++) {
        int rr = lr + p * 32;           // 0..127
        int s = rr & 63;
        sv[p] = *(const float4*)(sc + ((long)(b * SS + s)) * DD + lc4);
        wv[p] = *(const float4*)(w1 + (long)rr * DD + lc4);
    }

    for (int j2b = 0; j2b < 4; j2b++) {
        float acc[2][8][4];
#pragma unroll
        for (int mt = 0; mt < 2; mt++)
#pragma unroll
            for (int nt = 0; nt < 8; nt++)
#pragma unroll
                for (int q = 0; q < 4; q++) acc[mt][nt][q] = 0.f;

        for (int kc = 0; kc < 16; kc++) {
            const int k0 = kc << 5;
            // STS current (H = relu(fc+sc), W1 raw->tf32)
#pragma unroll
            for (int p = 0; p < 4; p++) {
                int rr = lr + p * 32;
                int i = rr >> 6;
                float4 fv = *(const float4*)(&fcb[i][k0 + lc4]);
                *(uint4*)&Hs[swz(rr, lc4)] = make_uint4(
                    f2t(fmaxf(sv[p].x + fv.x, 0.f)),
                    f2t(fmaxf(sv[p].y + fv.y, 0.f)),
                    f2t(fmaxf(sv[p].z + fv.z, 0.f)),
                    f2t(fmaxf(sv[p].w + fv.w, 0.f)));
                *(uint4*)&Ws[swz(rr, lc4)] =
                    make_uint4(f2t(wv[p].x), f2t(wv[p].y), f2t(wv[p].z), f2t(wv[p].w));
            }
            __syncthreads();
            // prefetch next position
            int nj = j2b, nkc = kc + 1;
            if (nkc == 16) { nj++; nkc = 0; }
            if (nj < 4) {
                const int k0n = nkc << 5;
#pragma unroll
                for (int p = 0; p < 4; p++) {
                    int rr = lr + p * 32;
                    int s = rr & 63;
                    sv[p] = *(const float4*)(sc + ((long)(b * SS + s)) * DD + k0n + lc4);
                    wv[p] = *(const float4*)(w1 + ((long)(nj * 128 + rr)) * DD + k0n + lc4);
                }
            }
            // compute
#pragma unroll
            for (int kk = 0; kk < 4; kk++) {
                const int kb = kk * 8;
                unsigned a[2][4], bfr[8][2];
#pragma unroll
                for (int mt = 0; mt < 2; mt++) {
                    int rb = wm * 32 + mt * 16;
                    a[mt][0] = Hs[swz(rb + g,     kb + tig)];
                    a[mt][1] = Hs[swz(rb + g + 8, kb + tig)];
                    a[mt][2] = Hs[swz(rb + g,     kb + tig + 4)];
                    a[mt][3] = Hs[swz(rb + g + 8, kb + tig + 4)];
                }
#pragma unroll
                for (int nt = 0; nt < 8; nt++) {
                    int n = wn * 64 + nt * 8 + g;
                    bfr[nt][0] = Ws[swz(n, kb + tig)];
                    bfr[nt][1] = Ws[swz(n, kb + tig + 4)];
                }
#pragma unroll
                for (int mt = 0; mt < 2; mt++)
#pragma unroll
                    for (int nt = 0; nt < 8; nt++)
                        mma8(acc[mt][nt], a[mt], bfr[nt]);
            }
            __syncthreads();
        }
        // epilogue: relu(+b1) . w2 over this 128-col block
#pragma unroll
        for (int mt = 0; mt < 2; mt++)
#pragma unroll
            for (int half = 0; half < 2; half++) {
                float acc_s = 0.f;
#pragma unroll
                for (int nt = 0; nt < 8; nt++) {
                    int c = j2b * 128 + wn * 64 + nt * 8 + 2 * tig;
                    float2 b1v = *(const float2*)(b1 + c);
                    float2 w2v = *(const float2*)(w2 + c);
                    acc_s += fmaxf(acc[mt][nt][half * 2] + b1v.x, 0.f) * w2v.x;
                    acc_s += fmaxf(acc[mt][nt][half * 2 + 1] + b1v.y, 0.f) * w2v.y;
                }
                pacc[mt][half] += acc_s;
            }
    }

    // reduce partial scores
#pragma unroll
    for (int mt = 0; mt < 2; mt++)
#pragma unroll
        for (int half = 0; half < 2; half++) {
            float v = pacc[mt][half];
            v += __shfl_down_sync(0xffffffffu, v, 2);
            v += __shfl_down_sync(0xffffffffu, v, 1);
            if (tig == 0)
                spart[wm * 32 + mt * 16 + g + half * 8][wn] = v;
        }
    __syncthreads();

    if (tid < 128) {
        float s = spart[tid][0] + spart[tid][1];
        scorebuf[tid >> 6][tid & 63] = s;
    }
    __syncthreads();

    if (wid < 2) {
        int i = wid;
        float v0 = scorebuf[i][lane], v1 = scorebuf[i][lane + 32];
        float m = fmaxf(v0, v1);
#pragma unroll
        for (int o = 16; o; o >>= 1) m = fmaxf(m, __shfl_xor_sync(0xffffffffu, m, o));
        float e0 = expf(v0 - m), e1 = expf(v1 - m);
        float ssum = e0 + e1;
#pragma unroll
        for (int o = 16; o; o >>= 1) ssum += __shfl_xor_sync(0xffffffffu, ssum, o);
        float inv = 1.f / ssum;
        abuf[i][lane] = e0 * inv;
        abuf[i][lane + 32] = e1 * inv;
    }
    __syncthreads();

#pragma unroll
    for (int p = 0; p < 4; p++) {
        int idx = p * 256 + tid;
        int i = idx >> 9, d = idx & 511;
        float a = 0.f;
#pragma unroll 4
        for (int s = 0; s < SS; s++)
            a += abuf[i][s] * sem[((long)(b * SS + s)) * DD + d];
        relk[((long)((2 * tp + i) * 32 + b)) * DD + d] = a;
    }
}

// ---------------------------------------------------------------------------
// Fused attention for Tk=64: scores + softmax + AV in one kernel.
// One CTA per (b,h). P overwrites Q tile; V overwrites K tile.
// ---------------------------------------------------------------------------
__global__ void __launch_bounds__(256)
attn_fused64(const float* __restrict__ q, int ldq,
             const float* __restrict__ k, int ldk,
             const float* __restrict__ v, int ldv,
             float* __restrict__ O)
{
    const int bh = blockIdx.x;
    const int b = bh >> 3, h = bh & 7;
    __shared__ __align__(16) float Qs[64][68];   // Q[q][e] -> later P[q][kt]
    __shared__ __align__(16) float Ks[64][68];   // K^T[e][kt] -> later V[kt][e]
    const int tid = threadIdx.x;
    const int tx = tid & 31, ty = tid >> 5;
    const float scale = 0.125f;

#pragma unroll
    for (int p = 0; p < 16; p++) {
        int idx = p * 256 + tid;
        int e = idx & 63, r = idx >> 6;
        Qs[r][e] = q[((long)(r * 32 + b)) * ldq + h * 64 + e];
        Ks[e][r] = k[((long)(r * 32 + b)) * ldk + h * 64 + e];
    }
    __syncthreads();

    float acc[8][2];
#pragma unroll
    for (int i = 0; i < 8; i++) { acc[i][0] = 0.f; acc[i][1] = 0.f; }
#pragma unroll 8
    for (int e = 0; e < 64; e++) {
        float b0v = Ks[e][tx * 2];
        float b1v = Ks[e][tx * 2 + 1];
#pragma unroll
        for (int i = 0; i < 8; i++) {
            float a = Qs[ty * 8 + i][e];
            acc[i][0] += a * b0v;
            acc[i][1] += a * b1v;
        }
    }
    // softmax per row (warp owns rows ty*8..+7; lanes cover 64 cols as 2 each),
    // write P in-place over this warp's own Q rows.
#pragma unroll
    for (int i = 0; i < 8; i++) {
        float v0 = acc[i][0] * scale, v1 = acc[i][1] * scale;
        float m = fmaxf(v0, v1);
#pragma unroll
        for (int o = 16; o; o >>= 1) m = fmaxf(m, __shfl_xor_sync(0xffffffffu, m, o));
        float e0 = expf(v0 - m), e1 = expf(v1 - m);
        float s = e0 + e1;
#pragma unroll
        for (int o = 16; o; o >>= 1) s += __shfl_xor_sync(0xffffffffu, s, o);
        float inv = 1.f / s;
        Qs[ty * 8 + i][tx * 2]     = e0 * inv;
        Qs[ty * 8 + i][tx * 2 + 1] = e1 * inv;
    }
    __syncthreads();   // everyone done reading K (and own Q rows rewritten)

    // V overwrites Ks as [kt][e]
#pragma unroll
    for (int p = 0; p < 16; p++) {
        int idx = p * 256 + tid;
        int e = idx & 63, r = idx >> 6;
        Ks[r][e] = v[((long)(r * 32 + b)) * ldv + h * 64 + e];
    }
    __syncthreads();

    float oacc[8][2];
#pragma unroll
    for (int i = 0; i < 8; i++) { oacc[i][0] = 0.f; oacc[i][1] = 0.f; }
#pragma unroll 8
    for (int kk = 0; kk < 64; kk++) {
        float b0v = Ks[kk][tx * 2];
        float b1v = Ks[kk][tx * 2 + 1];
#pragma unroll
        for (int i = 0; i < 8; i++) {
            float a = Qs[ty * 8 + i][kk];
            oacc[i][0] += a * b0v;
            oacc[i][1] += a * b1v;
        }
    }
#pragma unroll
    for (int i = 0; i < 8; i++) {
        int qr = ty * 8 + i;
        *(float2*)&O[((long)(qr * 32 + b)) * DD + h * 64 + tx * 2] =
            make_float2(oacc[i][0], oacc[i][1]);
    }
}

// ---------------------------------------------------------------------------
// ca path (Tk=256): scores / softmax / AV (unchanged)
// ---------------------------------------------------------------------------
__global__ void __launch_bounds__(256)
attn_scores_kernel(const float* __restrict__ q, int ldq,
                   const float* __restrict__ k, int ldk,
                   float* __restrict__ S, int Tk)
{
    const int bh = blockIdx.x;
    const int b = bh >> 3, h = bh & 7;
    __shared__ __align__(16) float Qs[64][72];
    __shared__ __align__(16) float Ks[64][72];
    const int tid = threadIdx.x;
    const int tx = tid & 31, ty = tid >> 5;
    const float scale = 0.125f;

#pragma unroll
    for (int p = 0; p < 16; p++) {
        int idx = p * 256 + tid;
        int e = idx & 63, r = idx >> 6;
        Qs[r][e] = q[((long)(r * 32 + b)) * ldq + h * 64 + e];
    }
    for (int kt0 = 0; kt0 < Tk; kt0 += 64) {
#pragma unroll
        for (int p = 0; p < 16; p++) {
            int idx = p * 256 + tid;
            int e = idx & 63, r = idx >> 6;
            Ks[e][r] = k[((long)((kt0 + r) * 32 + b)) * ldk + h * 64 + e];
        }
        __syncthreads();
        float acc[8][2];
#pragma unroll
        for (int i = 0; i < 8; i++) { acc[i][0] = 0.f; acc[i][1] = 0.f; }
#pragma unroll 8
        for (int e = 0; e < 64; e++) {
            float b0v = Ks[e][tx * 2];
            float b1v = Ks[e][tx * 2 + 1];
#pragma unroll
            for (int i = 0; i < 8; i++) {
                float a = Qs[ty * 8 + i][e];
                acc[i][0] += a * b0v;
                acc[i][1] += a * b1v;
            }
        }
#pragma unroll
        for (int i = 0; i < 8; i++) {
            int qr = ty * 8 + i;
            float2 v = make_float2(acc[i][0] * scale, acc[i][1] * scale);
            *(float2*)&S[((long)(bh * 64 + qr)) * MM + kt0 + tx * 2] = v;
        }
        __syncthreads();
    }
}

__global__ void __launch_bounds__(256)
softmax_rows_kernel(float* __restrict__ S, int Tk)
{
    const int row = blockIdx.x * 8 + (threadIdx.x >> 5);
    const int lane = threadIdx.x & 31;
    float* p = S + (long)row * MM;
    const int n = Tk >> 5;
    float vals[8];
    float m = -1e30f;
    for (int c = 0; c < n; c++) { vals[c] = p[lane + c * 32]; m = fmaxf(m, vals[c]); }
#pragma unroll
    for (int o = 16; o; o >>= 1) m = fmaxf(m, __shfl_xor_sync(0xffffffffu, m, o));
    float s = 0.f;
    for (int c = 0; c < n; c++) { vals[c] = expf(vals[c] - m); s += vals[c]; }
#pragma unroll
    for (int o = 16; o; o >>= 1) s += __shfl_xor_sync(0xffffffffu, s, o);
    const float inv = 1.f / s;
    for (int c = 0; c < n; c++) p[lane + c * 32] = vals[c] * inv;
}

__global__ void __launch_bounds__(256)
attn_av_kernel(const float* __restrict__ P, const float* __restrict__ v, int ldv,
               float* __restrict__ O, int Tk)
{
    const int bh = blockIdx.x;
    const int b = bh >> 3, h = bh & 7;
    __shared__ __align__(16) float Ps[64][72];
    __shared__ __align__(16) float Vs[64][72];
    const int tid = threadIdx.x;
    const int tx = tid & 31, ty = tid >> 5;

    float acc[8][2];
#pragma unroll
    for (int i = 0; i < 8; i++) { acc[i][0] = 0.f; acc[i][1] = 0.f; }

    for (int kt0 = 0; kt0 < Tk; kt0 += 64) {
#pragma unroll
        for (int p = 0; p < 16; p++) {
            int idx = p * 256 + tid;
            int kl = idx & 63, r = idx >> 6;
            Ps[r][kl] = P[((long)(bh * 64 + r)) * MM + kt0 + kl];
            Vs[r][kl] = v[((long)((kt0 + r) * 32 + b)) * ldv + h * 64 + kl];
        }
        __syncthreads();
#pragma unroll 8
        for (int kk = 0; kk < 64; kk++) {
            float b0v = Vs[kk][tx * 2];
            float b1v = Vs[kk][tx * 2 + 1];
#pragma unroll
            for (int i = 0; i < 8; i++) {
                float a = Ps[ty * 8 + i][kk];
                acc[i][0] += a * b0v;
                acc[i][1] += a * b1v;
            }
        }
        __syncthreads();
    }
#pragma unroll
    for (int i = 0; i < 8; i++) {
        int qr = ty * 8 + i;
        *(float2*)&O[((long)(qr * 32 + b)) * DD + h * 64 + tx * 2] =
            make_float2(acc[i][0], acc[i][1]);
    }
}

__global__ void __launch_bounds__(256)
layernorm_kernel(const float* __restrict__ x, const float* __restrict__ g,
                 const float* __restrict__ bb, float* __restrict__ out)
{
    const int row = blockIdx.x * 8 + (threadIdx.x >> 5);
    const int lane = threadIdx.x & 31;
    const float* p = x + (long)row * DD;
    float v[16];
    float s = 0.f;
#pragma unroll
    for (int c = 0; c < 16; c++) { v[c] = p[lane + c * 32]; s += v[c]; }
#pragma unroll
    for (int o = 16; o; o >>= 1) s += __shfl_xor_sync(0xffffffffu, s, o);
    const float mu = s * (1.f / DD);
    float q = 0.f;
#pragma unroll
    for (int c = 0; c < 16; c++) { float d = v[c] - mu; q += d * d; }
#pragma unroll
    for (int o = 16; o; o >>= 1) q += __shfl_xor_sync(0xffffffffu, q, o);
    const float rstd = rsqrtf(q * (1.f / DD) + 1e-5f);
#pragma unroll
    for (int c = 0; c < 16; c++) {
        int col = lane + c * 32;
        out[(long)row * DD + col] = (v[c] - mu) * rstd * g[col] + bb[col];
    }
}

// ---------------------------------------------------------------------------
// Host side
// ---------------------------------------------------------------------------
static inline void run_gemm(const float* A, int lda, const float* W, int ldw,
                            const float* bias, const float* resid, float* C,
                            int M, int N, int K, int relu)
{
    dim3 grid(N / 64, M / 64);
    gemm_tc<<<grid, 128>>>(A, lda, W, ldw, bias, resid, C, N, K, relu);
}

extern "C" void kernel_launch(void* const* d_in, const int* in_sizes, int n_in,
                              void* d_out, int out_size)
{
    const float* tgt      = (const float*)d_in[0];
    const float* memory   = (const float*)d_in[1];
    const float* sem      = (const float*)d_in[2];
    const float* pt_wqkv  = (const float*)d_in[3];
    const float* pt_bqkv  = (const float*)d_in[4];
    const float* pt_wo    = (const float*)d_in[5];
    const float* pt_bo    = (const float*)d_in[6];
    const float* sa_wqkv  = (const float*)d_in[7];
    const float* sa_bqkv  = (const float*)d_in[8];
    const float* sa_wo    = (const float*)d_in[9];
    const float* sa_bo    = (const float*)d_in[10];
    const float* ca_wqkv  = (const float*)d_in[11];
    const float* ca_bqkv  = (const float*)d_in[12];
    const float* ca_wo    = (const float*)d_in[13];
    const float* ca_bo    = (const float*)d_in[14];
    const float* mlp_w0   = (const float*)d_in[15];
    const float* mlp_b0   = (const float*)d_in[16];
    const float* mlp_w1   = (const float*)d_in[17];
    const float* mlp_b1   = (const float*)d_in[18];
    const float* mlp_w2   = (const float*)d_in[19];
    /* mlp_b2 shift-invariant under softmax -> unused */
    const float* ffn_w1   = (const float*)d_in[21];
    const float* ffn_b1   = (const float*)d_in[22];
    const float* ffn_w2   = (const float*)d_in[23];
    const float* ffn_b2   = (const float*)d_in[24];
    const float* ln1_g    = (const float*)d_in[25];
    const float* ln1_b    = (const float*)d_in[26];
    const float* ln2_g    = (const float*)d_in[27];
    const float* ln2_b    = (const float*)d_in[28];
    const float* ln3_g    = (const float*)d_in[29];
    const float* ln3_b    = (const float*)d_in[30];
    float* out = (float*)d_out;

    float *fc, *sc, *relk, *qb, *qkv, *kv, *Sb, *attn, *x1, *x2, *x3, *tmp, *ffh;
    cudaGetSymbolAddress((void**)&fc,   g_fc);
    cudaGetSymbolAddress((void**)&sc,   g_sc);
    cudaGetSymbolAddress((void**)&relk, g_relk);
    cudaGetSymbolAddress((void**)&qb,   g_qb);
    cudaGetSymbolAddress((void**)&qkv,  g_qkv);
    cudaGetSymbolAddress((void**)&kv,   g_kv);
    cudaGetSymbolAddress((void**)&Sb,   g_S);
    cudaGetSymbolAddress((void**)&attn, g_attn);
    cudaGetSymbolAddress((void**)&x1,   g_x1);
    cudaGetSymbolAddress((void**)&x2,   g_x2);
    cudaGetSymbolAddress((void**)&x3,   g_x3);
    cudaGetSymbolAddress((void**)&tmp,  g_tmp);
    cudaGetSymbolAddress((void**)&ffh,  g_ffh);

    // ---- relevant semantic -------------------------------------------------
    run_gemm(tgt, DD, mlp_w0,      2 * DD, nullptr, nullptr, fc, NTB,     DD, DD, 0);
    run_gemm(sem, DD, mlp_w0 + DD, 2 * DD, nullptr, nullptr, sc, BB * SS, DD, DD, 0);
    relevance_tc<<<NTB / 2, 256>>>(fc, sc, sem, mlp_b0, mlp_w1, mlp_b1, mlp_w2, relk);

    // ---- block 1: mha(tgt, sem_k, sem_k) + residual (no LN) ---------------
    run_gemm(tgt,  DD, pt_wqkv,           DD, pt_bqkv,      nullptr, qb, NTB, DD,     DD, 0);
    run_gemm(relk, DD, pt_wqkv + DD * DD, DD, pt_bqkv + DD, nullptr, kv, NTB, 2 * DD, DD, 0);
    attn_fused64<<<BB * HH, 256>>>(qb, DD, kv, 2 * DD, kv + DD, 2 * DD, attn);
    run_gemm(attn, DD, pt_wo, DD, pt_bo, tgt, x1, NTB, DD, DD, 0);

    // ---- block 2: self-attention + LN1 ------------------------------------
    run_gemm(x1, DD, sa_wqkv, DD, sa_bqkv, nullptr, qkv, NTB, 3 * DD, DD, 0);
    attn_fused64<<<BB * HH, 256>>>(qkv, 3 * DD, qkv + DD, 3 * DD, qkv + 2 * DD, 3 * DD, attn);
    run_gemm(attn, DD, sa_wo, DD, sa_bo, x1, tmp, NTB, DD, DD, 0);
    layernorm_kernel<<<NTB / 8, 256>>>(tmp, ln1_g, ln1_b, x2);

    // ---- block 3: cross-attention over memory + LN2 ------------------------
    run_gemm(x2,     DD, ca_wqkv,           DD, ca_bqkv,      nullptr, qb, NTB, DD,     DD, 0);
    run_gemm(memory, DD, ca_wqkv + DD * DD, DD, ca_bqkv + DD, nullptr, kv, NMB, 2 * DD, DD, 0);
    attn_scores_kernel<<<BB * HH, 256>>>(qb, DD, kv, 2 * DD, Sb, MM);
    softmax_rows_kernel<<<BB * HH * TT / 8, 256>>>(Sb, MM);
    attn_av_kernel<<<BB * HH, 256>>>(Sb, kv + DD, 2 * DD, attn, MM);
    run_gemm(attn, DD, ca_wo, DD, ca_bo, x2, tmp, NTB, DD, DD, 0);
    layernorm_kernel<<<NTB / 8, 256>>>(tmp, ln2_g, ln2_b, x3);

    // ---- FFN + LN3 ---------------------------------------------------------
    run_gemm(x3,  DD,  ffn_w1, DD,  ffn_b1, nullptr, ffh, NTB, FFD, DD,  1);
    run_gemm(ffh, FFD, ffn_w2, FFD, ffn_b2, x3,      tmp, NTB, DD,  FFD, 0);
    layernorm_kernel<<<NTB / 8, 256>>>(tmp, ln3_g, ln3_b, out);
}

// round 13
// speedup vs baseline: 3.5578x; 1.0983x over previous
#include <cuda_runtime.h>
#include <math.h>

// ---------------------------------------------------------------------------
// Problem constants
// ---------------------------------------------------------------------------
#define TT 64
#define BB 32
#define DD 512
#define HH 8
#define HD 64
#define SS 64
#define MM 256
#define FFD 2048
#define NTB (TT*BB)   // 2048
#define NMB (MM*BB)   // 8192

// ---------------------------------------------------------------------------
// Scratch (device globals; no allocation anywhere)
// ---------------------------------------------------------------------------
__device__ float g_fc  [NTB*DD];
__device__ float g_sc  [BB*SS*DD];
__device__ float g_relk[NTB*DD];
__device__ float g_qb  [NTB*DD];
__device__ float g_qkv [NTB*3*DD];
__device__ float g_kv  [NMB*2*DD];
__device__ float g_S   [BB*HH*TT*MM];
__device__ float g_attn[NTB*DD];
__device__ float g_x1  [NTB*DD];
__device__ float g_x2  [NTB*DD];
__device__ float g_x3  [NTB*DD];
__device__ float g_tmp [NTB*DD];
__device__ float g_ffh [NTB*FFD];

// ---------------------------------------------------------------------------
// tf32 / async-copy helpers
// ---------------------------------------------------------------------------
__device__ __forceinline__ unsigned f2t(float x) {
    unsigned u;
    asm("cvt.rna.tf32.f32 %0, %1;" : "=r"(u) : "f"(x));
    return u;
}
__device__ __forceinline__ void mma8(float* c, const unsigned* a, const unsigned* b) {
    asm volatile(
        "mma.sync.aligned.m16n8k8.row.col.f32.tf32.tf32.f32 "
        "{%0,%1,%2,%3}, {%4,%5,%6,%7}, {%8,%9}, {%0,%1,%2,%3};"
        : "+f"(c[0]), "+f"(c[1]), "+f"(c[2]), "+f"(c[3])
        : "r"(a[0]), "r"(a[1]), "r"(a[2]), "r"(a[3]), "r"(b[0]), "r"(b[1]));
}
__device__ __forceinline__ void cpa16(void* smem_dst, const void* gsrc) {
    unsigned saddr = (unsigned)__cvta_generic_to_shared(smem_dst);
    asm volatile("cp.async.cg.shared.global [%0], [%1], 16;" :: "r"(saddr), "l"(gsrc));
}
#define CPA_COMMIT()  asm volatile("cp.async.commit_group;")
#define CPA_WAIT(n)   asm volatile("cp.async.wait_group %0;" :: "n"(n))

// XOR swizzle: row stride 32 words, k-group permuted by row -> conflict-free
// fragment LDS and 4-phase-floor 16B STS/cp.async.
__device__ __forceinline__ int swz(int row, int k) {
    return (row << 5) + (k ^ ((row & 7) << 2));
}

// ---------------------------------------------------------------------------
// Tensor-core GEMM v3: C[M,N] = act(A[M,K](lda) @ W[N,K](ldw)^T + bias + resid)
// BM=64, BN=64, BK=32, 128 threads (4 warps as 2x2, warp tile 32x32).
// cp.async double-buffered smem ring (raw f32), cvt->tf32 at fragment load.
// ---------------------------------------------------------------------------
__global__ void __launch_bounds__(128)
gemm_tc(const float* __restrict__ A, int lda,
        const float* __restrict__ W, int ldw,
        const float* __restrict__ bias,
        const float* __restrict__ resid,
        float* __restrict__ C,
        int N, int K, int doRelu)
{
    __shared__ float As[2][64 * 32];
    __shared__ float Ws[2][64 * 32];
    const int tid = threadIdx.x;
    const int wid = tid >> 5, lane = tid & 31;
    const int g = lane >> 2, tig = lane & 3;
    const int wm = wid >> 1, wn = wid & 1;
    const int row0 = blockIdx.y * 64, col0 = blockIdx.x * 64;
    const float* Ab = A + (long)row0 * lda;
    const float* Wb = W + (long)col0 * ldw;
    const int lr = tid >> 3;            // 0..15 (+16 per p)
    const int lc4 = (tid & 7) << 2;     // 16B column
    const int nk = K >> 5;

    // preload stage 0
#pragma unroll
    for (int p = 0; p < 4; p++) {
        int r = lr + p * 16;
        cpa16(&As[0][swz(r, lc4)], Ab + (long)r * lda + lc4);
        cpa16(&Ws[0][swz(r, lc4)], Wb + (long)r * ldw + lc4);
    }
    CPA_COMMIT();

    float acc[2][4][4];
#pragma unroll
    for (int mt = 0; mt < 2; mt++)
#pragma unroll
        for (int nt = 0; nt < 4; nt++)
#pragma unroll
            for (int q = 0; q < 4; q++) acc[mt][nt][q] = 0.f;

    for (int kc = 0; kc < nk; kc++) {
        if (kc + 1 < nk) {
            const int k0 = (kc + 1) << 5;
            const int st = (kc + 1) & 1;
#pragma unroll
            for (int p = 0; p < 4; p++) {
                int r = lr + p * 16;
                cpa16(&As[st][swz(r, lc4)], Ab + (long)r * lda + k0 + lc4);
                cpa16(&Ws[st][swz(r, lc4)], Wb + (long)r * ldw + k0 + lc4);
            }
            CPA_COMMIT();
            CPA_WAIT(1);
        } else {
            CPA_WAIT(0);
        }
        __syncthreads();
        const float* as = As[kc & 1];
        const float* ws = Ws[kc & 1];
#pragma unroll
        for (int kk = 0; kk < 4; kk++) {
            const int kb = kk * 8;
            unsigned a[2][4], b[4][2];
#pragma unroll
            for (int mt = 0; mt < 2; mt++) {
                int rb = wm * 32 + mt * 16;
                a[mt][0] = f2t(as[swz(rb + g,     kb + tig)]);
                a[mt][1] = f2t(as[swz(rb + g + 8, kb + tig)]);
                a[mt][2] = f2t(as[swz(rb + g,     kb + tig + 4)]);
                a[mt][3] = f2t(as[swz(rb + g + 8, kb + tig + 4)]);
            }
#pragma unroll
            for (int nt = 0; nt < 4; nt++) {
                int n = wn * 32 + nt * 8 + g;
                b[nt][0] = f2t(ws[swz(n, kb + tig)]);
                b[nt][1] = f2t(ws[swz(n, kb + tig + 4)]);
            }
#pragma unroll
            for (int mt = 0; mt < 2; mt++)
#pragma unroll
                for (int nt = 0; nt < 4; nt++)
                    mma8(acc[mt][nt], a[mt], b[nt]);
        }
        __syncthreads();
    }

#pragma unroll
    for (int mt = 0; mt < 2; mt++)
#pragma unroll
        for (int half = 0; half < 2; half++) {
            const int r = row0 + wm * 32 + mt * 16 + g + half * 8;
#pragma unroll
            for (int nt = 0; nt < 4; nt++) {
                const int c = col0 + wn * 32 + nt * 8 + 2 * tig;
                float v0 = acc[mt][nt][half * 2];
                float v1 = acc[mt][nt][half * 2 + 1];
                if (bias) { v0 += bias[c]; v1 += bias[c + 1]; }
                if (resid) {
                    float2 rr = *(const float2*)(resid + (long)r * N + c);
                    v0 += rr.x; v1 += rr.y;
                }
                if (doRelu) { v0 = fmaxf(v0, 0.f); v1 = fmaxf(v1, 0.f); }
                *(float2*)(C + (long)r * N + c) = make_float2(v0, v1);
            }
        }
}

// ---------------------------------------------------------------------------
// Fused relevance, tensor-core + pipelined. One CTA per (t-pair, b).
// M-tile = 128 (2 rows x 64 s), N = 512 in 4 blocks of 128, K = 512.
// 8 warps as 4(M)x2(N), warp tile 32x64.  (unchanged this round)
// ---------------------------------------------------------------------------
__global__ void __launch_bounds__(256)
relevance_tc(const float* __restrict__ fc, const float* __restrict__ sc,
             const float* __restrict__ sem, const float* __restrict__ b0,
             const float* __restrict__ w1, const float* __restrict__ b1,
             const float* __restrict__ w2, float* __restrict__ relk)
{
    __shared__ float fcb[2][DD];
    __shared__ unsigned Hs[128 * 32];
    __shared__ unsigned Ws[128 * 32];
    __shared__ float spart[128][2];
    __shared__ float abuf[2][SS];
    __shared__ float scorebuf[2][SS];

    const int bid = blockIdx.x;
    const int b = bid & 31;
    const int tp = bid >> 5;
    const int tid = threadIdx.x;
    const int wid = tid >> 5, lane = tid & 31;
    const int g = lane >> 2, tig = lane & 3;
    const int wm = wid & 3, wn = wid >> 2;
    const int lr = tid >> 3;
    const int lc4 = (tid & 7) << 2;

#pragma unroll
    for (int p = 0; p < 4; p++) {
        int idx = p * 256 + tid;
        int i = idx >> 9, d = idx & 511;
        fcb[i][d] = fc[((long)((2 * tp + i) * 32 + b)) * DD + d] + b0[d];
    }
    __syncthreads();

    float pacc[2][2];
    pacc[0][0] = pacc[0][1] = pacc[1][0] = pacc[1][1] = 0.f;

    float4 sv[4], wv[4];
#pragma unroll
    for (int p = 0; p < 4; p++) {
        int rr = lr + p * 32;
        int s = rr & 63;
        sv[p] = *(const float4*)(sc + ((long)(b * SS + s)) * DD + lc4);
        wv[p] = *(const float4*)(w1 + (long)rr * DD + lc4);
    }

    for (int j2b = 0; j2b < 4; j2b++) {
        float acc[2][8][4];
#pragma unroll
        for (int mt = 0; mt < 2; mt++)
#pragma unroll
            for (int nt = 0; nt < 8; nt++)
#pragma unroll
                for (int q = 0; q < 4; q++) acc[mt][nt][q] = 0.f;

        for (int kc = 0; kc < 16; kc++) {
            const int k0 = kc << 5;
#pragma unroll
            for (int p = 0; p < 4; p++) {
                int rr = lr + p * 32;
                int i = rr >> 6;
                float4 fv = *(const float4*)(&fcb[i][k0 + lc4]);
                *(uint4*)&Hs[swz(rr, lc4)] = make_uint4(
                    f2t(fmaxf(sv[p].x + fv.x, 0.f)),
                    f2t(fmaxf(sv[p].y + fv.y, 0.f)),
                    f2t(fmaxf(sv[p].z + fv.z, 0.f)),
                    f2t(fmaxf(sv[p].w + fv.w, 0.f)));
                *(uint4*)&Ws[swz(rr, lc4)] =
                    make_uint4(f2t(wv[p].x), f2t(wv[p].y), f2t(wv[p].z), f2t(wv[p].w));
            }
            __syncthreads();
            int nj = j2b, nkc = kc + 1;
            if (nkc == 16) { nj++; nkc = 0; }
            if (nj < 4) {
                const int k0n = nkc << 5;
#pragma unroll
                for (int p = 0; p < 4; p++) {
                    int rr = lr + p * 32;
                    int s = rr & 63;
                    sv[p] = *(const float4*)(sc + ((long)(b * SS + s)) * DD + k0n + lc4);
                    wv[p] = *(const float4*)(w1 + ((long)(nj * 128 + rr)) * DD + k0n + lc4);
                }
            }
#pragma unroll
            for (int kk = 0; kk < 4; kk++) {
                const int kb = kk * 8;
                unsigned a[2][4], bfr[8][2];
#pragma unroll
                for (int mt = 0; mt < 2; mt++) {
                    int rb = wm * 32 + mt * 16;
                    a[mt][0] = Hs[swz(rb + g,     kb + tig)];
                    a[mt][1] = Hs[swz(rb + g + 8, kb + tig)];
                    a[mt][2] = Hs[swz(rb + g,     kb + tig + 4)];
                    a[mt][3] = Hs[swz(rb + g + 8, kb + tig + 4)];
                }
#pragma unroll
                for (int nt = 0; nt < 8; nt++) {
                    int n = wn * 64 + nt * 8 + g;
                    bfr[nt][0] = Ws[swz(n, kb + tig)];
                    bfr[nt][1] = Ws[swz(n, kb + tig + 4)];
                }
#pragma unroll
                for (int mt = 0; mt < 2; mt++)
#pragma unroll
                    for (int nt = 0; nt < 8; nt++)
                        mma8(acc[mt][nt], a[mt], bfr[nt]);
            }
            __syncthreads();
        }
#pragma unroll
        for (int mt = 0; mt < 2; mt++)
#pragma unroll
            for (int half = 0; half < 2; half++) {
                float acc_s = 0.f;
#pragma unroll
                for (int nt = 0; nt < 8; nt++) {
                    int c = j2b * 128 + wn * 64 + nt * 8 + 2 * tig;
                    float2 b1v = *(const float2*)(b1 + c);
                    float2 w2v = *(const float2*)(w2 + c);
                    acc_s += fmaxf(acc[mt][nt][half * 2] + b1v.x, 0.f) * w2v.x;
                    acc_s += fmaxf(acc[mt][nt][half * 2 + 1] + b1v.y, 0.f) * w2v.y;
                }
                pacc[mt][half] += acc_s;
            }
    }

#pragma unroll
    for (int mt = 0; mt < 2; mt++)
#pragma unroll
        for (int half = 0; half < 2; half++) {
            float v = pacc[mt][half];
            v += __shfl_down_sync(0xffffffffu, v, 2);
            v += __shfl_down_sync(0xffffffffu, v, 1);
            if (tig == 0)
                spart[wm * 32 + mt * 16 + g + half * 8][wn] = v;
        }
    __syncthreads();

    if (tid < 128) {
        float s = spart[tid][0] + spart[tid][1];
        scorebuf[tid >> 6][tid & 63] = s;
    }
    __syncthreads();

    if (wid < 2) {
        int i = wid;
        float v0 = scorebuf[i][lane], v1 = scorebuf[i][lane + 32];
        float m = fmaxf(v0, v1);
#pragma unroll
        for (int o = 16; o; o >>= 1) m = fmaxf(m, __shfl_xor_sync(0xffffffffu, m, o));
        float e0 = expf(v0 - m), e1 = expf(v1 - m);
        float ssum = e0 + e1;
#pragma unroll
        for (int o = 16; o; o >>= 1) ssum += __shfl_xor_sync(0xffffffffu, ssum, o);
        float inv = 1.f / ssum;
        abuf[i][lane] = e0 * inv;
        abuf[i][lane + 32] = e1 * inv;
    }
    __syncthreads();

#pragma unroll
    for (int p = 0; p < 4; p++) {
        int idx = p * 256 + tid;
        int i = idx >> 9, d = idx & 511;
        float a = 0.f;
#pragma unroll 4
        for (int s = 0; s < SS; s++)
            a += abuf[i][s] * sem[((long)(b * SS + s)) * DD + d];
        relk[((long)((2 * tp + i) * 32 + b)) * DD + d] = a;
    }
}

// ---------------------------------------------------------------------------
// Fused attention for Tk=64 (unchanged)
// ---------------------------------------------------------------------------
__global__ void __launch_bounds__(256)
attn_fused64(const float* __restrict__ q, int ldq,
             const float* __restrict__ k, int ldk,
             const float* __restrict__ v, int ldv,
             float* __restrict__ O)
{
    const int bh = blockIdx.x;
    const int b = bh >> 3, h = bh & 7;
    __shared__ __align__(16) float Qs[64][68];
    __shared__ __align__(16) float Ks[64][68];
    const int tid = threadIdx.x;
    const int tx = tid & 31, ty = tid >> 5;
    const float scale = 0.125f;

#pragma unroll
    for (int p = 0; p < 16; p++) {
        int idx = p * 256 + tid;
        int e = idx & 63, r = idx >> 6;
        Qs[r][e] = q[((long)(r * 32 + b)) * ldq + h * 64 + e];
        Ks[e][r] = k[((long)(r * 32 + b)) * ldk + h * 64 + e];
    }
    __syncthreads();

    float acc[8][2];
#pragma unroll
    for (int i = 0; i < 8; i++) { acc[i][0] = 0.f; acc[i][1] = 0.f; }
#pragma unroll 8
    for (int e = 0; e < 64; e++) {
        float b0v = Ks[e][tx * 2];
        float b1v = Ks[e][tx * 2 + 1];
#pragma unroll
        for (int i = 0; i < 8; i++) {
            float a = Qs[ty * 8 + i][e];
            acc[i][0] += a * b0v;
            acc[i][1] += a * b1v;
        }
    }
#pragma unroll
    for (int i = 0; i < 8; i++) {
        float v0 = acc[i][0] * scale, v1 = acc[i][1] * scale;
        float m = fmaxf(v0, v1);
#pragma unroll
        for (int o = 16; o; o >>= 1) m = fmaxf(m, __shfl_xor_sync(0xffffffffu, m, o));
        float e0 = expf(v0 - m), e1 = expf(v1 - m);
        float s = e0 + e1;
#pragma unroll
        for (int o = 16; o; o >>= 1) s += __shfl_xor_sync(0xffffffffu, s, o);
        float inv = 1.f / s;
        Qs[ty * 8 + i][tx * 2]     = e0 * inv;
        Qs[ty * 8 + i][tx * 2 + 1] = e1 * inv;
    }
    __syncthreads();

#pragma unroll
    for (int p = 0; p < 16; p++) {
        int idx = p * 256 + tid;
        int e = idx & 63, r = idx >> 6;
        Ks[r][e] = v[((long)(r * 32 + b)) * ldv + h * 64 + e];
    }
    __syncthreads();

    float oacc[8][2];
#pragma unroll
    for (int i = 0; i < 8; i++) { oacc[i][0] = 0.f; oacc[i][1] = 0.f; }
#pragma unroll 8
    for (int kk = 0; kk < 64; kk++) {
        float b0v = Ks[kk][tx * 2];
        float b1v = Ks[kk][tx * 2 + 1];
#pragma unroll
        for (int i = 0; i < 8; i++) {
            float a = Qs[ty * 8 + i][kk];
            oacc[i][0] += a * b0v;
            oacc[i][1] += a * b1v;
        }
    }
#pragma unroll
    for (int i = 0; i < 8; i++) {
        int qr = ty * 8 + i;
        *(float2*)&O[((long)(qr * 32 + b)) * DD + h * 64 + tx * 2] =
            make_float2(oacc[i][0], oacc[i][1]);
    }
}

// ---------------------------------------------------------------------------
// ca path (Tk=256): scores / softmax / AV (unchanged)
// ---------------------------------------------------------------------------
__global__ void __launch_bounds__(256)
attn_scores_kernel(const float* __restrict__ q, int ldq,
                   const float* __restrict__ k, int ldk,
                   float* __restrict__ S, int Tk)
{
    const int bh = blockIdx.x;
    const int b = bh >> 3, h = bh & 7;
    __shared__ __align__(16) float Qs[64][72];
    __shared__ __align__(16) float Ks[64][72];
    const int tid = threadIdx.x;
    const int tx = tid & 31, ty = tid >> 5;
    const float scale = 0.125f;

#pragma unroll
    for (int p = 0; p < 16; p++) {
        int idx = p * 256 + tid;
        int e = idx & 63, r = idx >> 6;
        Qs[r][e] = q[((long)(r * 32 + b)) * ldq + h * 64 + e];
    }
    for (int kt0 = 0; kt0 < Tk; kt0 += 64) {
#pragma unroll
        for (int p = 0; p < 16; p++) {
            int idx = p * 256 + tid;
            int e = idx & 63, r = idx >> 6;
            Ks[e][r] = k[((long)((kt0 + r) * 32 + b)) * ldk + h * 64 + e];
        }
        __syncthreads();
        float acc[8][2];
#pragma unroll
        for (int i = 0; i < 8; i++) { acc[i][0] = 0.f; acc[i][1] = 0.f; }
#pragma unroll 8
        for (int e = 0; e < 64; e++) {
            float b0v = Ks[e][tx * 2];
            float b1v = Ks[e][tx * 2 + 1];
#pragma unroll
            for (int i = 0; i < 8; i++) {
                float a = Qs[ty * 8 + i][e];
                acc[i][0] += a * b0v;
                acc[i][1] += a * b1v;
            }
        }
#pragma unroll
        for (int i = 0; i < 8; i++) {
            int qr = ty * 8 + i;
            float2 v = make_float2(acc[i][0] * scale, acc[i][1] * scale);
            *(float2*)&S[((long)(bh * 64 + qr)) * MM + kt0 + tx * 2] = v;
        }
        __syncthreads();
    }
}

__global__ void __launch_bounds__(256)
softmax_rows_kernel(float* __restrict__ S, int Tk)
{
    const int row = blockIdx.x * 8 + (threadIdx.x >> 5);
    const int lane = threadIdx.x & 31;
    float* p = S + (long)row * MM;
    const int n = Tk >> 5;
    float vals[8];
    float m = -1e30f;
    for (int c = 0; c < n; c++) { vals[c] = p[lane + c * 32]; m = fmaxf(m, vals[c]); }
#pragma unroll
    for (int o = 16; o; o >>= 1) m = fmaxf(m, __shfl_xor_sync(0xffffffffu, m, o));
    float s = 0.f;
    for (int c = 0; c < n; c++) { vals[c] = expf(vals[c] - m); s += vals[c]; }
#pragma unroll
    for (int o = 16; o; o >>= 1) s += __shfl_xor_sync(0xffffffffu, s, o);
    const float inv = 1.f / s;
    for (int c = 0; c < n; c++) p[lane + c * 32] = vals[c] * inv;
}

__global__ void __launch_bounds__(256)
attn_av_kernel(const float* __restrict__ P, const float* __restrict__ v, int ldv,
               float* __restrict__ O, int Tk)
{
    const int bh = blockIdx.x;
    const int b = bh >> 3, h = bh & 7;
    __shared__ __align__(16) float Ps[64][72];
    __shared__ __align__(16) float Vs[64][72];
    const int tid = threadIdx.x;
    const int tx = tid & 31, ty = tid >> 5;

    float acc[8][2];
#pragma unroll
    for (int i = 0; i < 8; i++) { acc[i][0] = 0.f; acc[i][1] = 0.f; }

    for (int kt0 = 0; kt0 < Tk; kt0 += 64) {
#pragma unroll
        for (int p = 0; p < 16; p++) {
            int idx = p * 256 + tid;
            int kl = idx & 63, r = idx >> 6;
            Ps[r][kl] = P[((long)(bh * 64 + r)) * MM + kt0 + kl];
            Vs[r][kl] = v[((long)((kt0 + r) * 32 + b)) * ldv + h * 64 + kl];
        }
        __syncthreads();
#pragma unroll 8
        for (int kk = 0; kk < 64; kk++) {
            float b0v = Vs[kk][tx * 2];
            float b1v = Vs[kk][tx * 2 + 1];
#pragma unroll
            for (int i = 0; i < 8; i++) {
                float a = Ps[ty * 8 + i][kk];
                acc[i][0] += a * b0v;
                acc[i][1] += a * b1v;
            }
        }
        __syncthreads();
    }
#pragma unroll
    for (int i = 0; i < 8; i++) {
        int qr = ty * 8 + i;
        *(float2*)&O[((long)(qr * 32 + b)) * DD + h * 64 + tx * 2] =
            make_float2(acc[i][0], acc[i][1]);
    }
}

__global__ void __launch_bounds__(256)
layernorm_kernel(const float* __restrict__ x, const float* __restrict__ g,
                 const float* __restrict__ bb, float* __restrict__ out)
{
    const int row = blockIdx.x * 8 + (threadIdx.x >> 5);
    const int lane = threadIdx.x & 31;
    const float* p = x + (long)row * DD;
    float v[16];
    float s = 0.f;
#pragma unroll
    for (int c = 0; c < 16; c++) { v[c] = p[lane + c * 32]; s += v[c]; }
#pragma unroll
    for (int o = 16; o; o >>= 1) s += __shfl_xor_sync(0xffffffffu, s, o);
    const float mu = s * (1.f / DD);
    float q = 0.f;
#pragma unroll
    for (int c = 0; c < 16; c++) { float d = v[c] - mu; q += d * d; }
#pragma unroll
    for (int o = 16; o; o >>= 1) q += __shfl_xor_sync(0xffffffffu, q, o);
    const float rstd = rsqrtf(q * (1.f / DD) + 1e-5f);
#pragma unroll
    for (int c = 0; c < 16; c++) {
        int col = lane + c * 32;
        out[(long)row * DD + col] = (v[c] - mu) * rstd * g[col] + bb[col];
    }
}

// ---------------------------------------------------------------------------
// Host side
// ---------------------------------------------------------------------------
static inline void run_gemm(const float* A, int lda, const float* W, int ldw,
                            const float* bias, const float* resid, float* C,
                            int M, int N, int K, int relu)
{
    dim3 grid(N / 64, M / 64);
    gemm_tc<<<grid, 128>>>(A, lda, W, ldw, bias, resid, C, N, K, relu);
}

extern "C" void kernel_launch(void* const* d_in, const int* in_sizes, int n_in,
                              void* d_out, int out_size)
{
    const float* tgt      = (const float*)d_in[0];
    const float* memory   = (const float*)d_in[1];
    const float* sem      = (const float*)d_in[2];
    const float* pt_wqkv  = (const float*)d_in[3];
    const float* pt_bqkv  = (const float*)d_in[4];
    const float* pt_wo    = (const float*)d_in[5];
    const float* pt_bo    = (const float*)d_in[6];
    const float* sa_wqkv  = (const float*)d_in[7];
    const float* sa_bqkv  = (const float*)d_in[8];
    const float* sa_wo    = (const float*)d_in[9];
    const float* sa_bo    = (const float*)d_in[10];
    const float* ca_wqkv  = (const float*)d_in[11];
    const float* ca_bqkv  = (const float*)d_in[12];
    const float* ca_wo    = (const float*)d_in[13];
    const float* ca_bo    = (const float*)d_in[14];
    const float* mlp_w0   = (const float*)d_in[15];
    const float* mlp_b0   = (const float*)d_in[16];
    const float* mlp_w1   = (const float*)d_in[17];
    const float* mlp_b1   = (const float*)d_in[18];
    const float* mlp_w2   = (const float*)d_in[19];
    /* mlp_b2 shift-invariant under softmax -> unused */
    const float* ffn_w1   = (const float*)d_in[21];
    const float* ffn_b1   = (const float*)d_in[22];
    const float* ffn_w2   = (const float*)d_in[23];
    const float* ffn_b2   = (const float*)d_in[24];
    const float* ln1_g    = (const float*)d_in[25];
    const float* ln1_b    = (const float*)d_in[26];
    const float* ln2_g    = (const float*)d_in[27];
    const float* ln2_b    = (const float*)d_in[28];
    const float* ln3_g    = (const float*)d_in[29];
    const float* ln3_b    = (const float*)d_in[30];
    float* out = (float*)d_out;

    float *fc, *sc, *relk, *qb, *qkv, *kv, *Sb, *attn, *x1, *x2, *x3, *tmp, *ffh;
    cudaGetSymbolAddress((void**)&fc,   g_fc);
    cudaGetSymbolAddress((void**)&sc,   g_sc);
    cudaGetSymbolAddress((void**)&relk, g_relk);
    cudaGetSymbolAddress((void**)&qb,   g_qb);
    cudaGetSymbolAddress((void**)&qkv,  g_qkv);
    cudaGetSymbolAddress((void**)&kv,   g_kv);
    cudaGetSymbolAddress((void**)&Sb,   g_S);
    cudaGetSymbolAddress((void**)&attn, g_attn);
    cudaGetSymbolAddress((void**)&x1,   g_x1);
    cudaGetSymbolAddress((void**)&x2,   g_x2);
    cudaGetSymbolAddress((void**)&x3,   g_x3);
    cudaGetSymbolAddress((void**)&tmp,  g_tmp);
    cudaGetSymbolAddress((void**)&ffh,  g_ffh);

    // ---- relevant semantic -------------------------------------------------
    run_gemm(tgt, DD, mlp_w0,      2 * DD, nullptr, nullptr, fc, NTB,     DD, DD, 0);
    run_gemm(sem, DD, mlp_w0 + DD, 2 * DD, nullptr, nullptr, sc, BB * SS, DD, DD, 0);
    relevance_tc<<<NTB / 2, 256>>>(fc, sc, sem, mlp_b0, mlp_w1, mlp_b1, mlp_w2, relk);

    // ---- block 1: mha(tgt, sem_k, sem_k) + residual (no LN) ---------------
    run_gemm(tgt,  DD, pt_wqkv,           DD, pt_bqkv,      nullptr, qb, NTB, DD,     DD, 0);
    run_gemm(relk, DD, pt_wqkv + DD * DD, DD, pt_bqkv + DD, nullptr, kv, NTB, 2 * DD, DD, 0);
    attn_fused64<<<BB * HH, 256>>>(qb, DD, kv, 2 * DD, kv + DD, 2 * DD, attn);
    run_gemm(attn, DD, pt_wo, DD, pt_bo, tgt, x1, NTB, DD, DD, 0);

    // ---- block 2: self-attention + LN1 ------------------------------------
    run_gemm(x1, DD, sa_wqkv, DD, sa_bqkv, nullptr, qkv, NTB, 3 * DD, DD, 0);
    attn_fused64<<<BB * HH, 256>>>(qkv, 3 * DD, qkv + DD, 3 * DD, qkv + 2 * DD, 3 * DD, attn);
    run_gemm(attn, DD, sa_wo, DD, sa_bo, x1, tmp, NTB, DD, DD, 0);
    layernorm_kernel<<<NTB / 8, 256>>>(tmp, ln1_g, ln1_b, x2);

    // ---- block 3: cross-attention over memory + LN2 ------------------------
    run_gemm(x2,     DD, ca_wqkv,           DD, ca_bqkv,      nullptr, qb, NTB, DD,     DD, 0);
    run_gemm(memory, DD, ca_wqkv + DD * DD, DD, ca_bqkv + DD, nullptr, kv, NMB, 2 * DD, DD, 0);
    attn_scores_kernel<<<BB * HH, 256>>>(qb, DD, kv, 2 * DD, Sb, MM);
    softmax_rows_kernel<<<BB * HH * TT / 8, 256>>>(Sb, MM);
    attn_av_kernel<<<BB * HH, 256>>>(Sb, kv + DD, 2 * DD, attn, MM);
    run_gemm(attn, DD, ca_wo, DD, ca_bo, x2, tmp, NTB, DD, DD, 0);
    layernorm_kernel<<<NTB / 8, 256>>>(tmp, ln2_g, ln2_b, x3);

    // ---- FFN + LN3 ---------------------------------------------------------
    run_gemm(x3,  DD,  ffn_w1, DD,  ffn_b1, nullptr, ffh, NTB, FFD, DD,  1);
    run_gemm(ffh, FFD, ffn_w2, FFD, ffn_b2, x3,      tmp, NTB, DD,  FFD, 0);
    layernorm_kernel<<<NTB / 8, 256>>>(tmp, ln3_g, ln3_b, out);
}

// round 16
// speedup vs baseline: 3.6182x; 1.0170x over previous
#include <cuda_runtime.h>
#include <math.h>

// ---------------------------------------------------------------------------
// Problem constants
// ---------------------------------------------------------------------------
#define TT 64
#define BB 32
#define DD 512
#define HH 8
#define HD 64
#define SS 64
#define MM 256
#define FFD 2048
#define NTB (TT*BB)   // 2048
#define NMB (MM*BB)   // 8192

// ---------------------------------------------------------------------------
// Scratch (device globals; no allocation anywhere)
// ---------------------------------------------------------------------------
__device__ float g_fc  [NTB*DD];
__device__ float g_sc  [BB*SS*DD];
__device__ float g_relk[NTB*DD];
__device__ float g_qb  [NTB*DD];
__device__ float g_qkv [NTB*3*DD];
__device__ float g_kv  [NMB*2*DD];
__device__ float g_S   [BB*HH*TT*MM];
__device__ float g_attn[NTB*DD];
__device__ float g_x1  [NTB*DD];
__device__ float g_x2  [NTB*DD];
__device__ float g_x3  [NTB*DD];
__device__ float g_tmp [NTB*DD];
__device__ float g_ffh [NTB*FFD];

// ---------------------------------------------------------------------------
// tf32 / async-copy helpers
// ---------------------------------------------------------------------------
__device__ __forceinline__ unsigned f2t(float x) {
    unsigned u;
    asm("cvt.rna.tf32.f32 %0, %1;" : "=r"(u) : "f"(x));
    return u;
}
__device__ __forceinline__ void mma8(float* c, const unsigned* a, const unsigned* b) {
    asm volatile(
        "mma.sync.aligned.m16n8k8.row.col.f32.tf32.tf32.f32 "
        "{%0,%1,%2,%3}, {%4,%5,%6,%7}, {%8,%9}, {%0,%1,%2,%3};"
        : "+f"(c[0]), "+f"(c[1]), "+f"(c[2]), "+f"(c[3])
        : "r"(a[0]), "r"(a[1]), "r"(a[2]), "r"(a[3]), "r"(b[0]), "r"(b[1]));
}
__device__ __forceinline__ void cpa16(void* smem_dst, const void* gsrc) {
    unsigned saddr = (unsigned)__cvta_generic_to_shared(smem_dst);
    asm volatile("cp.async.cg.shared.global [%0], [%1], 16;" :: "r"(saddr), "l"(gsrc));
}
#define CPA_COMMIT()  asm volatile("cp.async.commit_group;")
#define CPA_WAIT(n)   asm volatile("cp.async.wait_group %0;" :: "n"(n))

// XOR swizzle: row stride 32 words, k-group permuted by row -> conflict-free
// fragment LDS and 4-phase-floor 16B STS/cp.async.
__device__ __forceinline__ int swz(int row, int k) {
    return (row << 5) + (k ^ ((row & 7) << 2));
}

// ---------------------------------------------------------------------------
// Tensor-core GEMM v4: C[M,N] = act(A[M,K](lda) @ W[N,K](ldw)^T + bias + resid)
// BM=128, BN=64, BK=32, 256 threads (8 warps as 4x2, warp tile 32x32).
// cp.async double-buffered smem ring (raw f32), cvt->tf32 at fragment load.
// Single wave for the M=2048/N=512 GEMMs (128 CTAs on 148 SMs).
// ---------------------------------------------------------------------------
__global__ void __launch_bounds__(256)
gemm_tc(const float* __restrict__ A, int lda,
        const float* __restrict__ W, int ldw,
        const float* __restrict__ bias,
        const float* __restrict__ resid,
        float* __restrict__ C,
        int N, int K, int doRelu)
{
    __shared__ float As[2][128 * 32];
    __shared__ float Ws[2][64 * 32];
    const int tid = threadIdx.x;
    const int wid = tid >> 5, lane = tid & 31;
    const int g = lane >> 2, tig = lane & 3;
    const int wm = wid >> 1, wn = wid & 1;
    const int row0 = blockIdx.y * 128, col0 = blockIdx.x * 64;
    const float* Ab = A + (long)row0 * lda;
    const float* Wb = W + (long)col0 * ldw;
    const int lr = tid >> 3;            // 0..31 (+32 per p)
    const int lc4 = (tid & 7) << 2;     // 16B column
    const int nk = K >> 5;

    // preload stage 0
#pragma unroll
    for (int p = 0; p < 4; p++) {
        int r = lr + p * 32;
        cpa16(&As[0][swz(r, lc4)], Ab + (long)r * lda + lc4);
    }
#pragma unroll
    for (int p = 0; p < 2; p++) {
        int r = lr + p * 32;
        cpa16(&Ws[0][swz(r, lc4)], Wb + (long)r * ldw + lc4);
    }
    CPA_COMMIT();

    float acc[2][4][4];
#pragma unroll
    for (int mt = 0; mt < 2; mt++)
#pragma unroll
        for (int nt = 0; nt < 4; nt++)
#pragma unroll
            for (int q = 0; q < 4; q++) acc[mt][nt][q] = 0.f;

    for (int kc = 0; kc < nk; kc++) {
        if (kc + 1 < nk) {
            const int k0 = (kc + 1) << 5;
            const int st = (kc + 1) & 1;
#pragma unroll
            for (int p = 0; p < 4; p++) {
                int r = lr + p * 32;
                cpa16(&As[st][swz(r, lc4)], Ab + (long)r * lda + k0 + lc4);
            }
#pragma unroll
            for (int p = 0; p < 2; p++) {
                int r = lr + p * 32;
                cpa16(&Ws[st][swz(r, lc4)], Wb + (long)r * ldw + k0 + lc4);
            }
            CPA_COMMIT();
            CPA_WAIT(1);
        } else {
            CPA_WAIT(0);
        }
        __syncthreads();
        const float* as = As[kc & 1];
        const float* ws = Ws[kc & 1];
#pragma unroll
        for (int kk = 0; kk < 4; kk++) {
            const int kb = kk * 8;
            unsigned a[2][4], b[4][2];
#pragma unroll
            for (int mt = 0; mt < 2; mt++) {
                int rb = wm * 32 + mt * 16;
                a[mt][0] = f2t(as[swz(rb + g,     kb + tig)]);
                a[mt][1] = f2t(as[swz(rb + g + 8, kb + tig)]);
                a[mt][2] = f2t(as[swz(rb + g,     kb + tig + 4)]);
                a[mt][3] = f2t(as[swz(rb + g + 8, kb + tig + 4)]);
            }
#pragma unroll
            for (int nt = 0; nt < 4; nt++) {
                int n = wn * 32 + nt * 8 + g;
                b[nt][0] = f2t(ws[swz(n, kb + tig)]);
                b[nt][1] = f2t(ws[swz(n, kb + tig + 4)]);
            }
#pragma unroll
            for (int mt = 0; mt < 2; mt++)
#pragma unroll
                for (int nt = 0; nt < 4; nt++)
                    mma8(acc[mt][nt], a[mt], b[nt]);
        }
        __syncthreads();
    }

#pragma unroll
    for (int mt = 0; mt < 2; mt++)
#pragma unroll
        for (int half = 0; half < 2; half++) {
            const int r = row0 + wm * 32 + mt * 16 + g + half * 8;
#pragma unroll
            for (int nt = 0; nt < 4; nt++) {
                const int c = col0 + wn * 32 + nt * 8 + 2 * tig;
                float v0 = acc[mt][nt][half * 2];
                float v1 = acc[mt][nt][half * 2 + 1];
                if (bias) { v0 += bias[c]; v1 += bias[c + 1]; }
                if (resid) {
                    float2 rr = *(const float2*)(resid + (long)r * N + c);
                    v0 += rr.x; v1 += rr.y;
                }
                if (doRelu) { v0 = fmaxf(v0, 0.f); v1 = fmaxf(v1, 0.f); }
                *(float2*)(C + (long)r * N + c) = make_float2(v0, v1);
            }
        }
}

// ---------------------------------------------------------------------------
// Fused relevance v3: cp.async double-buffered sc/w1 chunks; H = relu(fc+sc)
// fused into the A-fragment load (no Hs buffer, no build phase).
// One CTA per (t-pair, b): M-tile 128 (2 t x 64 s), N = 512 in 4 j2b blocks,
// K = 512. 8 warps as 4(M)x2(N), warp tile 32x64.
// Dynamic smem: fcb[2*512] + scs[2][64*32] + wsb[2][128*32] = 53248 B.
// ---------------------------------------------------------------------------
__global__ void __launch_bounds__(256)
relevance_tc(const float* __restrict__ fc, const float* __restrict__ sc,
             const float* __restrict__ sem, const float* __restrict__ b0,
             const float* __restrict__ w1, const float* __restrict__ b1,
             const float* __restrict__ w2, float* __restrict__ relk)
{
    extern __shared__ float dsm[];
    float* fcb  = dsm;                    // [2][512]
    float* scsb = dsm + 1024;             // [2][64*32]
    float* wsbb = dsm + 1024 + 4096;      // [2][128*32]

    __shared__ float spart[128][2];
    __shared__ float abuf[2][SS];
    __shared__ float scorebuf[2][SS];

    const int bid = blockIdx.x;
    const int b = bid & 31;
    const int tp = bid >> 5;
    const int tid = threadIdx.x;
    const int wid = tid >> 5, lane = tid & 31;
    const int g = lane >> 2, tig = lane & 3;
    const int wm = wid & 3, wn = wid >> 2;
    const int lr = tid >> 3;              // 0..31 (+32 per p)
    const int lc4 = (tid & 7) << 2;

    // fcb = fc rows + b0
#pragma unroll
    for (int p = 0; p < 4; p++) {
        int idx = p * 256 + tid;
        int i = idx >> 9, d = idx & 511;
        fcb[i * DD + d] = fc[((long)((2 * tp + i) * 32 + b)) * DD + d] + b0[d];
    }

    // preload chunk 0 (j2b=0, kc=0) into stage 0
#pragma unroll
    for (int p = 0; p < 2; p++) {
        int s = lr + p * 32;
        cpa16(&scsb[swz(s, lc4)], sc + ((long)(b * SS + s)) * DD + lc4);
    }
#pragma unroll
    for (int p = 0; p < 4; p++) {
        int rr = lr + p * 32;
        cpa16(&wsbb[swz(rr, lc4)], w1 + (long)rr * DD + lc4);
    }
    CPA_COMMIT();
    __syncthreads();   // fcb ready

    float pacc[2][2];
    pacc[0][0] = pacc[0][1] = pacc[1][0] = pacc[1][1] = 0.f;

    for (int j2b = 0; j2b < 4; j2b++) {
        float acc[2][8][4];
#pragma unroll
        for (int mt = 0; mt < 2; mt++)
#pragma unroll
            for (int nt = 0; nt < 8; nt++)
#pragma unroll
                for (int q = 0; q < 4; q++) acc[mt][nt][q] = 0.f;

        for (int kc = 0; kc < 16; kc++) {
            const int c = j2b * 16 + kc;
            if (c + 1 < 64) {
                const int nj = (c + 1) >> 4, nkc = (c + 1) & 15;
                const int k0n = nkc << 5;
                const int st = (c + 1) & 1;
                float* scn = scsb + st * (64 * 32);
                float* wsn = wsbb + st * (128 * 32);
#pragma unroll
                for (int p = 0; p < 2; p++) {
                    int s = lr + p * 32;
                    cpa16(&scn[swz(s, lc4)],
                          sc + ((long)(b * SS + s)) * DD + k0n + lc4);
                }
#pragma unroll
                for (int p = 0; p < 4; p++) {
                    int rr = lr + p * 32;
                    cpa16(&wsn[swz(rr, lc4)],
                          w1 + ((long)(nj * 128 + rr)) * DD + k0n + lc4);
                }
                CPA_COMMIT();
                CPA_WAIT(1);
            } else {
                CPA_WAIT(0);
            }
            __syncthreads();
            const float* scc = scsb + (c & 1) * (64 * 32);
            const float* wsc = wsbb + (c & 1) * (128 * 32);
            const int k0 = kc << 5;
#pragma unroll
            for (int kk = 0; kk < 4; kk++) {
                const int kb = kk * 8;
                unsigned a[2][4], bfr[8][2];
#pragma unroll
                for (int mt = 0; mt < 2; mt++) {
                    int row = wm * 32 + mt * 16 + g;   // 0..127
                    int i = row >> 6;
                    int s0 = row & 63, s1 = (row + 8) & 63;
                    float f0 = fcb[i * DD + k0 + kb + tig];
                    float f4 = fcb[i * DD + k0 + kb + tig + 4];
                    a[mt][0] = f2t(fmaxf(scc[swz(s0, kb + tig)]     + f0, 0.f));
                    a[mt][1] = f2t(fmaxf(scc[swz(s1, kb + tig)]     + f0, 0.f));
                    a[mt][2] = f2t(fmaxf(scc[swz(s0, kb + tig + 4)] + f4, 0.f));
                    a[mt][3] = f2t(fmaxf(scc[swz(s1, kb + tig + 4)] + f4, 0.f));
                }
#pragma unroll
                for (int nt = 0; nt < 8; nt++) {
                    int n = wn * 64 + nt * 8 + g;
                    bfr[nt][0] = f2t(wsc[swz(n, kb + tig)]);
                    bfr[nt][1] = f2t(wsc[swz(n, kb + tig + 4)]);
                }
#pragma unroll
                for (int mt = 0; mt < 2; mt++)
#pragma unroll
                    for (int nt = 0; nt < 8; nt++)
                        mma8(acc[mt][nt], a[mt], bfr[nt]);
            }
            __syncthreads();
        }
        // epilogue: relu(+b1) . w2 over this 128-col block (registers only)
#pragma unroll
        for (int mt = 0; mt < 2; mt++)
#pragma unroll
            for (int half = 0; half < 2; half++) {
                float acc_s = 0.f;
#pragma unroll
                for (int nt = 0; nt < 8; nt++) {
                    int cc = j2b * 128 + wn * 64 + nt * 8 + 2 * tig;
                    float2 b1v = *(const float2*)(b1 + cc);
                    float2 w2v = *(const float2*)(w2 + cc);
                    acc_s += fmaxf(acc[mt][nt][half * 2] + b1v.x, 0.f) * w2v.x;
                    acc_s += fmaxf(acc[mt][nt][half * 2 + 1] + b1v.y, 0.f) * w2v.y;
                }
                pacc[mt][half] += acc_s;
            }
    }

    // reduce partial scores
#pragma unroll
    for (int mt = 0; mt < 2; mt++)
#pragma unroll
        for (int half = 0; half < 2; half++) {
            float v = pacc[mt][half];
            v += __shfl_down_sync(0xffffffffu, v, 2);
            v += __shfl_down_sync(0xffffffffu, v, 1);
            if (tig == 0)
                spart[wm * 32 + mt * 16 + g + half * 8][wn] = v;
        }
    __syncthreads();

    if (tid < 128) {
        float s = spart[tid][0] + spart[tid][1];
        scorebuf[tid >> 6][tid & 63] = s;
    }
    __syncthreads();

    if (wid < 2) {
        int i = wid;
        float v0 = scorebuf[i][lane], v1 = scorebuf[i][lane + 32];
        float m = fmaxf(v0, v1);
#pragma unroll
        for (int o = 16; o; o >>= 1) m = fmaxf(m, __shfl_xor_sync(0xffffffffu, m, o));
        float e0 = expf(v0 - m), e1 = expf(v1 - m);
        float ssum = e0 + e1;
#pragma unroll
        for (int o = 16; o; o >>= 1) ssum += __shfl_xor_sync(0xffffffffu, ssum, o);
        float inv = 1.f / ssum;
        abuf[i][lane] = e0 * inv;
        abuf[i][lane + 32] = e1 * inv;
    }
    __syncthreads();

#pragma unroll
    for (int p = 0; p < 4; p++) {
        int idx = p * 256 + tid;
        int i = idx >> 9, d = idx & 511;
        float a = 0.f;
#pragma unroll 4
        for (int s = 0; s < SS; s++)
            a += abuf[i][s] * sem[((long)(b * SS + s)) * DD + d];
        relk[((long)((2 * tp + i) * 32 + b)) * DD + d] = a;
    }
}

// ---------------------------------------------------------------------------
// Fused attention for Tk=64 (unchanged)
// ---------------------------------------------------------------------------
__global__ void __launch_bounds__(256)
attn_fused64(const float* __restrict__ q, int ldq,
             const float* __restrict__ k, int ldk,
             const float* __restrict__ v, int ldv,
             float* __restrict__ O)
{
    const int bh = blockIdx.x;
    const int b = bh >> 3, h = bh & 7;
    __shared__ __align__(16) float Qs[64][68];
    __shared__ __align__(16) float Ks[64][68];
    const int tid = threadIdx.x;
    const int tx = tid & 31, ty = tid >> 5;
    const float scale = 0.125f;

#pragma unroll
    for (int p = 0; p < 16; p++) {
        int idx = p * 256 + tid;
        int e = idx & 63, r = idx >> 6;
        Qs[r][e] = q[((long)(r * 32 + b)) * ldq + h * 64 + e];
        Ks[e][r] = k[((long)(r * 32 + b)) * ldk + h * 64 + e];
    }
    __syncthreads();

    float acc[8][2];
#pragma unroll
    for (int i = 0; i < 8; i++) { acc[i][0] = 0.f; acc[i][1] = 0.f; }
#pragma unroll 8
    for (int e = 0; e < 64; e++) {
        float b0v = Ks[e][tx * 2];
        float b1v = Ks[e][tx * 2 + 1];
#pragma unroll
        for (int i = 0; i < 8; i++) {
            float a = Qs[ty * 8 + i][e];
            acc[i][0] += a * b0v;
            acc[i][1] += a * b1v;
        }
    }
#pragma unroll
    for (int i = 0; i < 8; i++) {
        float v0 = acc[i][0] * scale, v1 = acc[i][1] * scale;
        float m = fmaxf(v0, v1);
#pragma unroll
        for (int o = 16; o; o >>= 1) m = fmaxf(m, __shfl_xor_sync(0xffffffffu, m, o));
        float e0 = expf(v0 - m), e1 = expf(v1 - m);
        float s = e0 + e1;
#pragma unroll
        for (int o = 16; o; o >>= 1) s += __shfl_xor_sync(0xffffffffu, s, o);
        float inv = 1.f / s;
        Qs[ty * 8 + i][tx * 2]     = e0 * inv;
        Qs[ty * 8 + i][tx * 2 + 1] = e1 * inv;
    }
    __syncthreads();

#pragma unroll
    for (int p = 0; p < 16; p++) {
        int idx = p * 256 + tid;
        int e = idx & 63, r = idx >> 6;
        Ks[r][e] = v[((long)(r * 32 + b)) * ldv + h * 64 + e];
    }
    __syncthreads();

    float oacc[8][2];
#pragma unroll
    for (int i = 0; i < 8; i++) { oacc[i][0] = 0.f; oacc[i][1] = 0.f; }
#pragma unroll 8
    for (int kk = 0; kk < 64; kk++) {
        float b0v = Ks[kk][tx * 2];
        float b1v = Ks[kk][tx * 2 + 1];
#pragma unroll
        for (int i = 0; i < 8; i++) {
            float a = Qs[ty * 8 + i][kk];
            oacc[i][0] += a * b0v;
            oacc[i][1] += a * b1v;
        }
    }
#pragma unroll
    for (int i = 0; i < 8; i++) {
        int qr = ty * 8 + i;
        *(float2*)&O[((long)(qr * 32 + b)) * DD + h * 64 + tx * 2] =
            make_float2(oacc[i][0], oacc[i][1]);
    }
}

// ---------------------------------------------------------------------------
// ca path (Tk=256): scores / softmax / AV (unchanged)
// ---------------------------------------------------------------------------
__global__ void __launch_bounds__(256)
attn_scores_kernel(const float* __restrict__ q, int ldq,
                   const float* __restrict__ k, int ldk,
                   float* __restrict__ S, int Tk)
{
    const int bh = blockIdx.x;
    const int b = bh >> 3, h = bh & 7;
    __shared__ __align__(16) float Qs[64][72];
    __shared__ __align__(16) float Ks[64][72];
    const int tid = threadIdx.x;
    const int tx = tid & 31, ty = tid >> 5;
    const float scale = 0.125f;

#pragma unroll
    for (int p = 0; p < 16; p++) {
        int idx = p * 256 + tid;
        int e = idx & 63, r = idx >> 6;
        Qs[r][e] = q[((long)(r * 32 + b)) * ldq + h * 64 + e];
    }
    for (int kt0 = 0; kt0 < Tk; kt0 += 64) {
#pragma unroll
        for (int p = 0; p < 16; p++) {
            int idx = p * 256 + tid;
            int e = idx & 63, r = idx >> 6;
            Ks[e][r] = k[((long)((kt0 + r) * 32 + b)) * ldk + h * 64 + e];
        }
        __syncthreads();
        float acc[8][2];
#pragma unroll
        for (int i = 0; i < 8; i++) { acc[i][0] = 0.f; acc[i][1] = 0.f; }
#pragma unroll 8
        for (int e = 0; e < 64; e++) {
            float b0v = Ks[e][tx * 2];
            float b1v = Ks[e][tx * 2 + 1];
#pragma unroll
            for (int i = 0; i < 8; i++) {
                float a = Qs[ty * 8 + i][e];
                acc[i][0] += a * b0v;
                acc[i][1] += a * b1v;
            }
        }
#pragma unroll
        for (int i = 0; i < 8; i++) {
            int qr = ty * 8 + i;
            float2 v = make_float2(acc[i][0] * scale, acc[i][1] * scale);
            *(float2*)&S[((long)(bh * 64 + qr)) * MM + kt0 + tx * 2] = v;
        }
        __syncthreads();
    }
}

__global__ void __launch_bounds__(256)
softmax_rows_kernel(float* __restrict__ S, int Tk)
{
    const int row = blockIdx.x * 8 + (threadIdx.x >> 5);
    const int lane = threadIdx.x & 31;
    float* p = S + (long)row * MM;
    const int n = Tk >> 5;
    float vals[8];
    float m = -1e30f;
    for (int c = 0; c < n; c++) { vals[c] = p[lane + c * 32]; m = fmaxf(m, vals[c]); }
#pragma unroll
    for (int o = 16; o; o >>= 1) m = fmaxf(m, __shfl_xor_sync(0xffffffffu, m, o));
    float s = 0.f;
    for (int c = 0; c < n; c++) { vals[c] = expf(vals[c] - m); s += vals[c]; }
#pragma unroll
    for (int o = 16; o; o >>= 1) s += __shfl_xor_sync(0xffffffffu, s, o);
    const float inv = 1.f / s;
    for (int c = 0; c < n; c++) p[lane + c * 32] = vals[c] * inv;
}

__global__ void __launch_bounds__(256)
attn_av_kernel(const float* __restrict__ P, const float* __restrict__ v, int ldv,
               float* __restrict__ O, int Tk)
{
    const int bh = blockIdx.x;
    const int b = bh >> 3, h = bh & 7;
    __shared__ __align__(16) float Ps[64][72];
    __shared__ __align__(16) float Vs[64][72];
    const int tid = threadIdx.x;
    const int tx = tid & 31, ty = tid >> 5;

    float acc[8][2];
#pragma unroll
    for (int i = 0; i < 8; i++) { acc[i][0] = 0.f; acc[i][1] = 0.f; }

    for (int kt0 = 0; kt0 < Tk; kt0 += 64) {
#pragma unroll
        for (int p = 0; p < 16; p++) {
            int idx = p * 256 + tid;
            int kl = idx & 63, r = idx >> 6;
            Ps[r][kl] = P[((long)(bh * 64 + r)) * MM + kt0 + kl];
            Vs[r][kl] = v[((long)((kt0 + r) * 32 + b)) * ldv + h * 64 + kl];
        }
        __syncthreads();
#pragma unroll 8
        for (int kk = 0; kk < 64; kk++) {
            float b0v = Vs[kk][tx * 2];
            float b1v = Vs[kk][tx * 2 + 1];
#pragma unroll
            for (int i = 0; i < 8; i++) {
                float a = Ps[ty * 8 + i][kk];
                acc[i][0] += a * b0v;
                acc[i][1] += a * b1v;
            }
        }
        __syncthreads();
    }
#pragma unroll
    for (int i = 0; i < 8; i++) {
        int qr = ty * 8 + i;
        *(float2*)&O[((long)(qr * 32 + b)) * DD + h * 64 + tx * 2] =
            make_float2(acc[i][0], acc[i][1]);
    }
}

__global__ void __launch_bounds__(256)
layernorm_kernel(const float* __restrict__ x, const float* __restrict__ g,
                 const float* __restrict__ bb, float* __restrict__ out)
{
    const int row = blockIdx.x * 8 + (threadIdx.x >> 5);
    const int lane = threadIdx.x & 31;
    const float* p = x + (long)row * DD;
    float v[16];
    float s = 0.f;
#pragma unroll
    for (int c = 0; c < 16; c++) { v[c] = p[lane + c * 32]; s += v[c]; }
#pragma unroll
    for (int o = 16; o; o >>= 1) s += __shfl_xor_sync(0xffffffffu, s, o);
    const float mu = s * (1.f / DD);
    float q = 0.f;
#pragma unroll
    for (int c = 0; c < 16; c++) { float d = v[c] - mu; q += d * d; }
#pragma unroll
    for (int o = 16; o; o >>= 1) q += __shfl_xor_sync(0xffffffffu, q, o);
    const float rstd = rsqrtf(q * (1.f / DD) + 1e-5f);
#pragma unroll
    for (int c = 0; c < 16; c++) {
        int col = lane + c * 32;
        out[(long)row * DD + col] = (v[c] - mu) * rstd * g[col] + bb[col];
    }
}

// ---------------------------------------------------------------------------
// Host side
// ---------------------------------------------------------------------------
#define REL_SMEM 53248

static inline void run_gemm(const float* A, int lda, const float* W, int ldw,
                            const float* bias, const float* resid, float* C,
                            int M, int N, int K, int relu)
{
    dim3 grid(N / 64, M / 128);
    gemm_tc<<<grid, 256>>>(A, lda, W, ldw, bias, resid, C, N, K, relu);
}

extern "C" void kernel_launch(void* const* d_in, const int* in_sizes, int n_in,
                              void* d_out, int out_size)
{
    const float* tgt      = (const float*)d_in[0];
    const float* memory   = (const float*)d_in[1];
    const float* sem      = (const float*)d_in[2];
    const float* pt_wqkv  = (const float*)d_in[3];
    const float* pt_bqkv  = (const float*)d_in[4];
    const float* pt_wo    = (const float*)d_in[5];
    const float* pt_bo    = (const float*)d_in[6];
    const float* sa_wqkv  = (const float*)d_in[7];
    const float* sa_bqkv  = (const float*)d_in[8];
    const float* sa_wo    = (const float*)d_in[9];
    const float* sa_bo    = (const float*)d_in[10];
    const float* ca_wqkv  = (const float*)d_in[11];
    const float* ca_bqkv  = (const float*)d_in[12];
    const float* ca_wo    = (const float*)d_in[13];
    const float* ca_bo    = (const float*)d_in[14];
    const float* mlp_w0   = (const float*)d_in[15];
    const float* mlp_b0   = (const float*)d_in[16];
    const float* mlp_w1   = (const float*)d_in[17];
    const float* mlp_b1   = (const float*)d_in[18];
    const float* mlp_w2   = (const float*)d_in[19];
    /* mlp_b2 shift-invariant under softmax -> unused */
    const float* ffn_w1   = (const float*)d_in[21];
    const float* ffn_b1   = (const float*)d_in[22];
    const float* ffn_w2   = (const float*)d_in[23];
    const float* ffn_b2   = (const float*)d_in[24];
    const float* ln1_g    = (const float*)d_in[25];
    const float* ln1_b    = (const float*)d_in[26];
    const float* ln2_g    = (const float*)d_in[27];
    const float* ln2_b    = (const float*)d_in[28];
    const float* ln3_g    = (const float*)d_in[29];
    const float* ln3_b    = (const float*)d_in[30];
    float* out = (float*)d_out;

    float *fc, *sc, *relk, *qb, *qkv, *kv, *Sb, *attn, *x1, *x2, *x3, *tmp, *ffh;
    cudaGetSymbolAddress((void**)&fc,   g_fc);
    cudaGetSymbolAddress((void**)&sc,   g_sc);
    cudaGetSymbolAddress((void**)&relk, g_relk);
    cudaGetSymbolAddress((void**)&qb,   g_qb);
    cudaGetSymbolAddress((void**)&qkv,  g_qkv);
    cudaGetSymbolAddress((void**)&kv,   g_kv);
    cudaGetSymbolAddress((void**)&Sb,   g_S);
    cudaGetSymbolAddress((void**)&attn, g_attn);
    cudaGetSymbolAddress((void**)&x1,   g_x1);
    cudaGetSymbolAddress((void**)&x2,   g_x2);
    cudaGetSymbolAddress((void**)&x3,   g_x3);
    cudaGetSymbolAddress((void**)&tmp,  g_tmp);
    cudaGetSymbolAddress((void**)&ffh,  g_ffh);

    cudaFuncSetAttribute(relevance_tc,
                         cudaFuncAttributeMaxDynamicSharedMemorySize, REL_SMEM);

    // ---- relevant semantic -------------------------------------------------
    run_gemm(tgt, DD, mlp_w0,      2 * DD, nullptr, nullptr, fc, NTB,     DD, DD, 0);
    run_gemm(sem, DD, mlp_w0 + DD, 2 * DD, nullptr, nullptr, sc, BB * SS, DD, DD, 0);
    relevance_tc<<<NTB / 2, 256, REL_SMEM>>>(fc, sc, sem, mlp_b0, mlp_w1,
                                             mlp_b1, mlp_w2, relk);

    // ---- block 1: mha(tgt, sem_k, sem_k) + residual (no LN) ---------------
    run_gemm(tgt,  DD, pt_wqkv,           DD, pt_bqkv,      nullptr, qb, NTB, DD,     DD, 0);
    run_gemm(relk, DD, pt_wqkv + DD * DD, DD, pt_bqkv + DD, nullptr, kv, NTB, 2 * DD, DD, 0);
    attn_fused64<<<BB * HH, 256>>>(qb, DD, kv, 2 * DD, kv + DD, 2 * DD, attn);
    run_gemm(attn, DD, pt_wo, DD, pt_bo, tgt, x1, NTB, DD, DD, 0);

    // ---- block 2: self-attention + LN1 ------------------------------------
    run_gemm(x1, DD, sa_wqkv, DD, sa_bqkv, nullptr, qkv, NTB, 3 * DD, DD, 0);
    attn_fused64<<<BB * HH, 256>>>(qkv, 3 * DD, qkv + DD, 3 * DD, qkv + 2 * DD, 3 * DD, attn);
    run_gemm(attn, DD, sa_wo, DD, sa_bo, x1, tmp, NTB, DD, DD, 0);
    layernorm_kernel<<<NTB / 8, 256>>>(tmp, ln1_g, ln1_b, x2);

    // ---- block 3: cross-attention over memory + LN2 ------------------------
    run_gemm(x2,     DD, ca_wqkv,           DD, ca_bqkv,      nullptr, qb, NTB, DD,     DD, 0);
    run_gemm(memory, DD, ca_wqkv + DD * DD, DD, ca_bqkv + DD, nullptr, kv, NMB, 2 * DD, DD, 0);
    attn_scores_kernel<<<BB * HH, 256>>>(qb, DD, kv, 2 * DD, Sb, MM);
    softmax_rows_kernel<<<BB * HH * TT / 8, 256>>>(Sb, MM);
    attn_av_kernel<<<BB * HH, 256>>>(Sb, kv + DD, 2 * DD, attn, MM);
    run_gemm(attn, DD, ca_wo, DD, ca_bo, x2, tmp, NTB, DD, DD, 0);
    layernorm_kernel<<<NTB / 8, 256>>>(tmp, ln2_g, ln2_b, x3);

    // ---- FFN + LN3 ---------------------------------------------------------
    run_gemm(x3,  DD,  ffn_w1, DD,  ffn_b1, nullptr, ffh, NTB, FFD, DD,  1);
    run_gemm(ffh, FFD, ffn_w2, FFD, ffn_b2, x3,      tmp, NTB, DD,  FFD, 0);
    layernorm_kernel<<<NTB / 8, 256>>>(tmp, ln3_g, ln3_b, out);
}

// round 17
// speedup vs baseline: 3.6500x; 1.0088x over previous
#include <cuda_runtime.h>
#include <math.h>

// ---------------------------------------------------------------------------
// Problem constants
// ---------------------------------------------------------------------------
#define TT 64
#define BB 32
#define DD 512
#define HH 8
#define HD 64
#define SS 64
#define MM 256
#define FFD 2048
#define NTB (TT*BB)   // 2048
#define NMB (MM*BB)   // 8192

// ---------------------------------------------------------------------------
// Scratch (device globals; no allocation anywhere)
// ---------------------------------------------------------------------------
__device__ float g_fc  [NTB*DD];
__device__ float g_sc  [BB*SS*DD];
__device__ float g_relk[NTB*DD];
__device__ float g_qb  [NTB*DD];
__device__ float g_qkv [NTB*3*DD];
__device__ float g_kv  [NMB*2*DD];
__device__ float g_S   [BB*HH*TT*MM];
__device__ float g_attn[NTB*DD];
__device__ float g_x1  [NTB*DD];
__device__ float g_x2  [NTB*DD];
__device__ float g_x3  [NTB*DD];
__device__ float g_tmp [NTB*DD];
__device__ float g_ffh [NTB*FFD];

// ---------------------------------------------------------------------------
// tf32 / async-copy helpers
// ---------------------------------------------------------------------------
__device__ __forceinline__ unsigned f2t(float x) {
    unsigned u;
    asm("cvt.rna.tf32.f32 %0, %1;" : "=r"(u) : "f"(x));
    return u;
}
__device__ __forceinline__ void mma8(float* c, const unsigned* a, const unsigned* b) {
    asm volatile(
        "mma.sync.aligned.m16n8k8.row.col.f32.tf32.tf32.f32 "
        "{%0,%1,%2,%3}, {%4,%5,%6,%7}, {%8,%9}, {%0,%1,%2,%3};"
        : "+f"(c[0]), "+f"(c[1]), "+f"(c[2]), "+f"(c[3])
        : "r"(a[0]), "r"(a[1]), "r"(a[2]), "r"(a[3]), "r"(b[0]), "r"(b[1]));
}
__device__ __forceinline__ void cpa16(void* smem_dst, const void* gsrc) {
    unsigned saddr = (unsigned)__cvta_generic_to_shared(smem_dst);
    asm volatile("cp.async.cg.shared.global [%0], [%1], 16;" :: "r"(saddr), "l"(gsrc));
}
#define CPA_COMMIT()  asm volatile("cp.async.commit_group;")
#define CPA_WAIT(n)   asm volatile("cp.async.wait_group %0;" :: "n"(n))

// XOR swizzle: row stride 32 words, k-group permuted by row -> conflict-free
// fragment LDS and 4-phase-floor 16B STS/cp.async.
__device__ __forceinline__ int swz(int row, int k) {
    return (row << 5) + (k ^ ((row & 7) << 2));
}

// ---------------------------------------------------------------------------
// Tensor-core GEMM v5: C[M,N] = act(A[M,K](lda) @ W[N,K](ldw)^T + bias + resid)
// BM=64, BN=64, BK=32, 128 threads (4 warps as 2x2, warp tile 32x32).
// THREE-stage cp.async ring (48 KB static smem exactly) -> 3-4 CTAs/SM,
// 12-16 warps/SM for latency hiding. cvt->tf32 at fragment load.
// ---------------------------------------------------------------------------
__global__ void __launch_bounds__(128)
gemm_tc(const float* __restrict__ A, int lda,
        const float* __restrict__ W, int ldw,
        const float* __restrict__ bias,
        const float* __restrict__ resid,
        float* __restrict__ C,
        int N, int K, int doRelu)
{
    __shared__ float As[3][64 * 32];
    __shared__ float Ws[3][64 * 32];
    const int tid = threadIdx.x;
    const int wid = tid >> 5, lane = tid & 31;
    const int g = lane >> 2, tig = lane & 3;
    const int wm = wid >> 1, wn = wid & 1;
    const int row0 = blockIdx.y * 64, col0 = blockIdx.x * 64;
    const float* Ab = A + (long)row0 * lda;
    const float* Wb = W + (long)col0 * ldw;
    const int lr = tid >> 3;            // 0..15 (+16 per p)
    const int lc4 = (tid & 7) << 2;     // 16B column
    const int nk = K >> 5;

    // preload stages 0 and 1
#pragma unroll
    for (int s = 0; s < 2; s++) {
        const int k0 = s << 5;
#pragma unroll
        for (int p = 0; p < 4; p++) {
            int r = lr + p * 16;
            cpa16(&As[s][swz(r, lc4)], Ab + (long)r * lda + k0 + lc4);
            cpa16(&Ws[s][swz(r, lc4)], Wb + (long)r * ldw + k0 + lc4);
        }
        CPA_COMMIT();
    }

    float acc[2][4][4];
#pragma unroll
    for (int mt = 0; mt < 2; mt++)
#pragma unroll
        for (int nt = 0; nt < 4; nt++)
#pragma unroll
            for (int q = 0; q < 4; q++) acc[mt][nt][q] = 0.f;

    int st_w = 2;                 // stage to write next
    for (int kc = 0; kc < nk; kc++) {
        if (kc + 2 < nk) {
            const int k0 = (kc + 2) << 5;
#pragma unroll
            for (int p = 0; p < 4; p++) {
                int r = lr + p * 16;
                cpa16(&As[st_w][swz(r, lc4)], Ab + (long)r * lda + k0 + lc4);
                cpa16(&Ws[st_w][swz(r, lc4)], Wb + (long)r * ldw + k0 + lc4);
            }
            CPA_COMMIT();
            CPA_WAIT(2);
        } else if (kc + 1 < nk) {
            CPA_WAIT(1);
        } else {
            CPA_WAIT(0);
        }
        __syncthreads();
        const int st_r = st_w + 1 >= 3 ? st_w - 2 : st_w + 1;  // == kc % 3
        const float* as = As[st_r];
        const float* ws = Ws[st_r];
#pragma unroll
        for (int kk = 0; kk < 4; kk++) {
            const int kb = kk * 8;
            unsigned a[2][4], b[4][2];
#pragma unroll
            for (int mt = 0; mt < 2; mt++) {
                int rb = wm * 32 + mt * 16;
                a[mt][0] = f2t(as[swz(rb + g,     kb + tig)]);
                a[mt][1] = f2t(as[swz(rb + g + 8, kb + tig)]);
                a[mt][2] = f2t(as[swz(rb + g,     kb + tig + 4)]);
                a[mt][3] = f2t(as[swz(rb + g + 8, kb + tig + 4)]);
            }
#pragma unroll
            for (int nt = 0; nt < 4; nt++) {
                int n = wn * 32 + nt * 8 + g;
                b[nt][0] = f2t(ws[swz(n, kb + tig)]);
                b[nt][1] = f2t(ws[swz(n, kb + tig + 4)]);
            }
#pragma unroll
            for (int mt = 0; mt < 2; mt++)
#pragma unroll
                for (int nt = 0; nt < 4; nt++)
                    mma8(acc[mt][nt], a[mt], b[nt]);
        }
        __syncthreads();
        st_w = st_w + 1 >= 3 ? 0 : st_w + 1;
    }

#pragma unroll
    for (int mt = 0; mt < 2; mt++)
#pragma unroll
        for (int half = 0; half < 2; half++) {
            const int r = row0 + wm * 32 + mt * 16 + g + half * 8;
#pragma unroll
            for (int nt = 0; nt < 4; nt++) {
                const int c = col0 + wn * 32 + nt * 8 + 2 * tig;
                float v0 = acc[mt][nt][half * 2];
                float v1 = acc[mt][nt][half * 2 + 1];
                if (bias) { v0 += bias[c]; v1 += bias[c + 1]; }
                if (resid) {
                    float2 rr = *(const float2*)(resid + (long)r * N + c);
                    v0 += rr.x; v1 += rr.y;
                }
                if (doRelu) { v0 = fmaxf(v0, 0.f); v1 = fmaxf(v1, 0.f); }
                *(float2*)(C + (long)r * N + c) = make_float2(v0, v1);
            }
        }
}

// ---------------------------------------------------------------------------
// Fused relevance v3 (unchanged this round): cp.async double-buffered sc/w1;
// H = relu(fc+sc) fused into the A-fragment load.
// ---------------------------------------------------------------------------
__global__ void __launch_bounds__(256)
relevance_tc(const float* __restrict__ fc, const float* __restrict__ sc,
             const float* __restrict__ sem, const float* __restrict__ b0,
             const float* __restrict__ w1, const float* __restrict__ b1,
             const float* __restrict__ w2, float* __restrict__ relk)
{
    extern __shared__ float dsm[];
    float* fcb  = dsm;                    // [2][512]
    float* scsb = dsm + 1024;             // [2][64*32]
    float* wsbb = dsm + 1024 + 4096;      // [2][128*32]

    __shared__ float spart[128][2];
    __shared__ float abuf[2][SS];
    __shared__ float scorebuf[2][SS];

    const int bid = blockIdx.x;
    const int b = bid & 31;
    const int tp = bid >> 5;
    const int tid = threadIdx.x;
    const int wid = tid >> 5, lane = tid & 31;
    const int g = lane >> 2, tig = lane & 3;
    const int wm = wid & 3, wn = wid >> 2;
    const int lr = tid >> 3;              // 0..31 (+32 per p)
    const int lc4 = (tid & 7) << 2;

    // fcb = fc rows + b0
#pragma unroll
    for (int p = 0; p < 4; p++) {
        int idx = p * 256 + tid;
        int i = idx >> 9, d = idx & 511;
        fcb[i * DD + d] = fc[((long)((2 * tp + i) * 32 + b)) * DD + d] + b0[d];
    }

    // preload chunk 0 (j2b=0, kc=0) into stage 0
#pragma unroll
    for (int p = 0; p < 2; p++) {
        int s = lr + p * 32;
        cpa16(&scsb[swz(s, lc4)], sc + ((long)(b * SS + s)) * DD + lc4);
    }
#pragma unroll
    for (int p = 0; p < 4; p++) {
        int rr = lr + p * 32;
        cpa16(&wsbb[swz(rr, lc4)], w1 + (long)rr * DD + lc4);
    }
    CPA_COMMIT();
    __syncthreads();   // fcb ready

    float pacc[2][2];
    pacc[0][0] = pacc[0][1] = pacc[1][0] = pacc[1][1] = 0.f;

    for (int j2b = 0; j2b < 4; j2b++) {
        float acc[2][8][4];
#pragma unroll
        for (int mt = 0; mt < 2; mt++)
#pragma unroll
            for (int nt = 0; nt < 8; nt++)
#pragma unroll
                for (int q = 0; q < 4; q++) acc[mt][nt][q] = 0.f;

        for (int kc = 0; kc < 16; kc++) {
            const int c = j2b * 16 + kc;
            if (c + 1 < 64) {
                const int nj = (c + 1) >> 4, nkc = (c + 1) & 15;
                const int k0n = nkc << 5;
                const int st = (c + 1) & 1;
                float* scn = scsb + st * (64 * 32);
                float* wsn = wsbb + st * (128 * 32);
#pragma unroll
                for (int p = 0; p < 2; p++) {
                    int s = lr + p * 32;
                    cpa16(&scn[swz(s, lc4)],
                          sc + ((long)(b * SS + s)) * DD + k0n + lc4);
                }
#pragma unroll
                for (int p = 0; p < 4; p++) {
                    int rr = lr + p * 32;
                    cpa16(&wsn[swz(rr, lc4)],
                          w1 + ((long)(nj * 128 + rr)) * DD + k0n + lc4);
                }
                CPA_COMMIT();
                CPA_WAIT(1);
            } else {
                CPA_WAIT(0);
            }
            __syncthreads();
            const float* scc = scsb + (c & 1) * (64 * 32);
            const float* wsc = wsbb + (c & 1) * (128 * 32);
            const int k0 = kc << 5;
#pragma unroll
            for (int kk = 0; kk < 4; kk++) {
                const int kb = kk * 8;
                unsigned a[2][4], bfr[8][2];
#pragma unroll
                for (int mt = 0; mt < 2; mt++) {
                    int row = wm * 32 + mt * 16 + g;   // 0..127
                    int i = row >> 6;
                    int s0 = row & 63, s1 = (row + 8) & 63;
                    float f0 = fcb[i * DD + k0 + kb + tig];
                    float f4 = fcb[i * DD + k0 + kb + tig + 4];
                    a[mt][0] = f2t(fmaxf(scc[swz(s0, kb + tig)]     + f0, 0.f));
                    a[mt][1] = f2t(fmaxf(scc[swz(s1, kb + tig)]     + f0, 0.f));
                    a[mt][2] = f2t(fmaxf(scc[swz(s0, kb + tig + 4)] + f4, 0.f));
                    a[mt][3] = f2t(fmaxf(scc[swz(s1, kb + tig + 4)] + f4, 0.f));
                }
#pragma unroll
                for (int nt = 0; nt < 8; nt++) {
                    int n = wn * 64 + nt * 8 + g;
                    bfr[nt][0] = f2t(wsc[swz(n, kb + tig)]);
                    bfr[nt][1] = f2t(wsc[swz(n, kb + tig + 4)]);
                }
#pragma unroll
                for (int mt = 0; mt < 2; mt++)
#pragma unroll
                    for (int nt = 0; nt < 8; nt++)
                        mma8(acc[mt][nt], a[mt], bfr[nt]);
            }
            __syncthreads();
        }
        // epilogue: relu(+b1) . w2 over this 128-col block (registers only)
#pragma unroll
        for (int mt = 0; mt < 2; mt++)
#pragma unroll
            for (int half = 0; half < 2; half++) {
                float acc_s = 0.f;
#pragma unroll
                for (int nt = 0; nt < 8; nt++) {
                    int cc = j2b * 128 + wn * 64 + nt * 8 + 2 * tig;
                    float2 b1v = *(const float2*)(b1 + cc);
                    float2 w2v = *(const float2*)(w2 + cc);
                    acc_s += fmaxf(acc[mt][nt][half * 2] + b1v.x, 0.f) * w2v.x;
                    acc_s += fmaxf(acc[mt][nt][half * 2 + 1] + b1v.y, 0.f) * w2v.y;
                }
                pacc[mt][half] += acc_s;
            }
    }

    // reduce partial scores
#pragma unroll
    for (int mt = 0; mt < 2; mt++)
#pragma unroll
        for (int half = 0; half < 2; half++) {
            float v = pacc[mt][half];
            v += __shfl_down_sync(0xffffffffu, v, 2);
            v += __shfl_down_sync(0xffffffffu, v, 1);
            if (tig == 0)
                spart[wm * 32 + mt * 16 + g + half * 8][wn] = v;
        }
    __syncthreads();

    if (tid < 128) {
        float s = spart[tid][0] + spart[tid][1];
        scorebuf[tid >> 6][tid & 63] = s;
    }
    __syncthreads();

    if (wid < 2) {
        int i = wid;
        float v0 = scorebuf[i][lane], v1 = scorebuf[i][lane + 32];
        float m = fmaxf(v0, v1);
#pragma unroll
        for (int o = 16; o; o >>= 1) m = fmaxf(m, __shfl_xor_sync(0xffffffffu, m, o));
        float e0 = expf(v0 - m), e1 = expf(v1 - m);
        float ssum = e0 + e1;
#pragma unroll
        for (int o = 16; o; o >>= 1) ssum += __shfl_xor_sync(0xffffffffu, ssum, o);
        float inv = 1.f / ssum;
        abuf[i][lane] = e0 * inv;
        abuf[i][lane + 32] = e1 * inv;
    }
    __syncthreads();

#pragma unroll
    for (int p = 0; p < 4; p++) {
        int idx = p * 256 + tid;
        int i = idx >> 9, d = idx & 511;
        float a = 0.f;
#pragma unroll 4
        for (int s = 0; s < SS; s++)
            a += abuf[i][s] * sem[((long)(b * SS + s)) * DD + d];
        relk[((long)((2 * tp + i) * 32 + b)) * DD + d] = a;
    }
}

// ---------------------------------------------------------------------------
// Fused attention for Tk=64 (unchanged)
// ---------------------------------------------------------------------------
__global__ void __launch_bounds__(256)
attn_fused64(const float* __restrict__ q, int ldq,
             const float* __restrict__ k, int ldk,
             const float* __restrict__ v, int ldv,
             float* __restrict__ O)
{
    const int bh = blockIdx.x;
    const int b = bh >> 3, h = bh & 7;
    __shared__ __align__(16) float Qs[64][68];
    __shared__ __align__(16) float Ks[64][68];
    const int tid = threadIdx.x;
    const int tx = tid & 31, ty = tid >> 5;
    const float scale = 0.125f;

#pragma unroll
    for (int p = 0; p < 16; p++) {
        int idx = p * 256 + tid;
        int e = idx & 63, r = idx >> 6;
        Qs[r][e] = q[((long)(r * 32 + b)) * ldq + h * 64 + e];
        Ks[e][r] = k[((long)(r * 32 + b)) * ldk + h * 64 + e];
    }
    __syncthreads();

    float acc[8][2];
#pragma unroll
    for (int i = 0; i < 8; i++) { acc[i][0] = 0.f; acc[i][1] = 0.f; }
#pragma unroll 8
    for (int e = 0; e < 64; e++) {
        float b0v = Ks[e][tx * 2];
        float b1v = Ks[e][tx * 2 + 1];
#pragma unroll
        for (int i = 0; i < 8; i++) {
            float a = Qs[ty * 8 + i][e];
            acc[i][0] += a * b0v;
            acc[i][1] += a * b1v;
        }
    }
#pragma unroll
    for (int i = 0; i < 8; i++) {
        float v0 = acc[i][0] * scale, v1 = acc[i][1] * scale;
        float m = fmaxf(v0, v1);
#pragma unroll
        for (int o = 16; o; o >>= 1) m = fmaxf(m, __shfl_xor_sync(0xffffffffu, m, o));
        float e0 = expf(v0 - m), e1 = expf(v1 - m);
        float s = e0 + e1;
#pragma unroll
        for (int o = 16; o; o >>= 1) s += __shfl_xor_sync(0xffffffffu, s, o);
        float inv = 1.f / s;
        Qs[ty * 8 + i][tx * 2]     = e0 * inv;
        Qs[ty * 8 + i][tx * 2 + 1] = e1 * inv;
    }
    __syncthreads();

#pragma unroll
    for (int p = 0; p < 16; p++) {
        int idx = p * 256 + tid;
        int e = idx & 63, r = idx >> 6;
        Ks[r][e] = v[((long)(r * 32 + b)) * ldv + h * 64 + e];
    }
    __syncthreads();

    float oacc[8][2];
#pragma unroll
    for (int i = 0; i < 8; i++) { oacc[i][0] = 0.f; oacc[i][1] = 0.f; }
#pragma unroll 8
    for (int kk = 0; kk < 64; kk++) {
        float b0v = Ks[kk][tx * 2];
        float b1v = Ks[kk][tx * 2 + 1];
#pragma unroll
        for (int i = 0; i < 8; i++) {
            float a = Qs[ty * 8 + i][kk];
            oacc[i][0] += a * b0v;
            oacc[i][1] += a * b1v;
        }
    }
#pragma unroll
    for (int i = 0; i < 8; i++) {
        int qr = ty * 8 + i;
        *(float2*)&O[((long)(qr * 32 + b)) * DD + h * 64 + tx * 2] =
            make_float2(oacc[i][0], oacc[i][1]);
    }
}

// ---------------------------------------------------------------------------
// ca path (Tk=256): scores / softmax / AV (unchanged)
// ---------------------------------------------------------------------------
__global__ void __launch_bounds__(256)
attn_scores_kernel(const float* __restrict__ q, int ldq,
                   const float* __restrict__ k, int ldk,
                   float* __restrict__ S, int Tk)
{
    const int bh = blockIdx.x;
    const int b = bh >> 3, h = bh & 7;
    __shared__ __align__(16) float Qs[64][72];
    __shared__ __align__(16) float Ks[64][72];
    const int tid = threadIdx.x;
    const int tx = tid & 31, ty = tid >> 5;
    const float scale = 0.125f;

#pragma unroll
    for (int p = 0; p < 16; p++) {
        int idx = p * 256 + tid;
        int e = idx & 63, r = idx >> 6;
        Qs[r][e] = q[((long)(r * 32 + b)) * ldq + h * 64 + e];
    }
    for (int kt0 = 0; kt0 < Tk; kt0 += 64) {
#pragma unroll
        for (int p = 0; p < 16; p++) {
            int idx = p * 256 + tid;
            int e = idx & 63, r = idx >> 6;
            Ks[e][r] = k[((long)((kt0 + r) * 32 + b)) * ldk + h * 64 + e];
        }
        __syncthreads();
        float acc[8][2];
#pragma unroll
        for (int i = 0; i < 8; i++) { acc[i][0] = 0.f; acc[i][1] = 0.f; }
#pragma unroll 8
        for (int e = 0; e < 64; e++) {
            float b0v = Ks[e][tx * 2];
            float b1v = Ks[e][tx * 2 + 1];
#pragma unroll
            for (int i = 0; i < 8; i++) {
                float a = Qs[ty * 8 + i][e];
                acc[i][0] += a * b0v;
                acc[i][1] += a * b1v;
            }
        }
#pragma unroll
        for (int i = 0; i < 8; i++) {
            int qr = ty * 8 + i;
            float2 v = make_float2(acc[i][0] * scale, acc[i][1] * scale);
            *(float2*)&S[((long)(bh * 64 + qr)) * MM + kt0 + tx * 2] = v;
        }
        __syncthreads();
    }
}

__global__ void __launch_bounds__(256)
softmax_rows_kernel(float* __restrict__ S, int Tk)
{
    const int row = blockIdx.x * 8 + (threadIdx.x >> 5);
    const int lane = threadIdx.x & 31;
    float* p = S + (long)row * MM;
    const int n = Tk >> 5;
    float vals[8];
    float m = -1e30f;
    for (int c = 0; c < n; c++) { vals[c] = p[lane + c * 32]; m = fmaxf(m, vals[c]); }
#pragma unroll
    for (int o = 16; o; o >>= 1) m = fmaxf(m, __shfl_xor_sync(0xffffffffu, m, o));
    float s = 0.f;
    for (int c = 0; c < n; c++) { vals[c] = expf(vals[c] - m); s += vals[c]; }
#pragma unroll
    for (int o = 16; o; o >>= 1) s += __shfl_xor_sync(0xffffffffu, s, o);
    const float inv = 1.f / s;
    for (int c = 0; c < n; c++) p[lane + c * 32] = vals[c] * inv;
}

__global__ void __launch_bounds__(256)
attn_av_kernel(const float* __restrict__ P, const float* __restrict__ v, int ldv,
               float* __restrict__ O, int Tk)
{
    const int bh = blockIdx.x;
    const int b = bh >> 3, h = bh & 7;
    __shared__ __align__(16) float Ps[64][72];
    __shared__ __align__(16) float Vs[64][72];
    const int tid = threadIdx.x;
    const int tx = tid & 31, ty = tid >> 5;

    float acc[8][2];
#pragma unroll
    for (int i = 0; i < 8; i++) { acc[i][0] = 0.f; acc[i][1] = 0.f; }

    for (int kt0 = 0; kt0 < Tk; kt0 += 64) {
#pragma unroll
        for (int p = 0; p < 16; p++) {
            int idx = p * 256 + tid;
            int kl = idx & 63, r = idx >> 6;
            Ps[r][kl] = P[((long)(bh * 64 + r)) * MM + kt0 + kl];
            Vs[r][kl] = v[((long)((kt0 + r) * 32 + b)) * ldv + h * 64 + kl];
        }
        __syncthreads();
#pragma unroll 8
        for (int kk = 0; kk < 64; kk++) {
            float b0v = Vs[kk][tx * 2];
            float b1v = Vs[kk][tx * 2 + 1];
#pragma unroll
            for (int i = 0; i < 8; i++) {
                float a = Ps[ty * 8 + i][kk];
                acc[i][0] += a * b0v;
                acc[i][1] += a * b1v;
            }
        }
        __syncthreads();
    }
#pragma unroll
    for (int i = 0; i < 8; i++) {
        int qr = ty * 8 + i;
        *(float2*)&O[((long)(qr * 32 + b)) * DD + h * 64 + tx * 2] =
            make_float2(acc[i][0], acc[i][1]);
    }
}

__global__ void __launch_bounds__(256)
layernorm_kernel(const float* __restrict__ x, const float* __restrict__ g,
                 const float* __restrict__ bb, float* __restrict__ out)
{
    const int row = blockIdx.x * 8 + (threadIdx.x >> 5);
    const int lane = threadIdx.x & 31;
    const float* p = x + (long)row * DD;
    float v[16];
    float s = 0.f;
#pragma unroll
    for (int c = 0; c < 16; c++) { v[c] = p[lane + c * 32]; s += v[c]; }
#pragma unroll
    for (int o = 16; o; o >>= 1) s += __shfl_xor_sync(0xffffffffu, s, o);
    const float mu = s * (1.f / DD);
    float q = 0.f;
#pragma unroll
    for (int c = 0; c < 16; c++) { float d = v[c] - mu; q += d * d; }
#pragma unroll
    for (int o = 16; o; o >>= 1) q += __shfl_xor_sync(0xffffffffu, q, o);
    const float rstd = rsqrtf(q * (1.f / DD) + 1e-5f);
#pragma unroll
    for (int c = 0; c < 16; c++) {
        int col = lane + c * 32;
        out[(long)row * DD + col] = (v[c] - mu) * rstd * g[col] + bb[col];
    }
}

// ---------------------------------------------------------------------------
// Host side
// ---------------------------------------------------------------------------
#define REL_SMEM 53248

static inline void run_gemm(const float* A, int lda, const float* W, int ldw,
                            const float* bias, const float* resid, float* C,
                            int M, int N, int K, int relu)
{
    dim3 grid(N / 64, M / 64);
    gemm_tc<<<grid, 128>>>(A, lda, W, ldw, bias, resid, C, N, K, relu);
}

extern "C" void kernel_launch(void* const* d_in, const int* in_sizes, int n_in,
                              void* d_out, int out_size)
{
    const float* tgt      = (const float*)d_in[0];
    const float* memory   = (const float*)d_in[1];
    const float* sem      = (const float*)d_in[2];
    const float* pt_wqkv  = (const float*)d_in[3];
    const float* pt_bqkv  = (const float*)d_in[4];
    const float* pt_wo    = (const float*)d_in[5];
    const float* pt_bo    = (const float*)d_in[6];
    const float* sa_wqkv  = (const float*)d_in[7];
    const float* sa_bqkv  = (const float*)d_in[8];
    const float* sa_wo    = (const float*)d_in[9];
    const float* sa_bo    = (const float*)d_in[10];
    const float* ca_wqkv  = (const float*)d_in[11];
    const float* ca_bqkv  = (const float*)d_in[12];
    const float* ca_wo    = (const float*)d_in[13];
    const float* ca_bo    = (const float*)d_in[14];
    const float* mlp_w0   = (const float*)d_in[15];
    const float* mlp_b0   = (const float*)d_in[16];
    const float* mlp_w1   = (const float*)d_in[17];
    const float* mlp_b1   = (const float*)d_in[18];
    const float* mlp_w2   = (const float*)d_in[19];
    /* mlp_b2 shift-invariant under softmax -> unused */
    const float* ffn_w1   = (const float*)d_in[21];
    const float* ffn_b1   = (const float*)d_in[22];
    const float* ffn_w2   = (const float*)d_in[23];
    const float* ffn_b2   = (const float*)d_in[24];
    const float* ln1_g    = (const float*)d_in[25];
    const float* ln1_b    = (const float*)d_in[26];
    const float* ln2_g    = (const float*)d_in[27];
    const float* ln2_b    = (const float*)d_in[28];
    const float* ln3_g    = (const float*)d_in[29];
    const float* ln3_b    = (const float*)d_in[30];
    float* out = (float*)d_out;

    float *fc, *sc, *relk, *qb, *qkv, *kv, *Sb, *attn, *x1, *x2, *x3, *tmp, *ffh;
    cudaGetSymbolAddress((void**)&fc,   g_fc);
    cudaGetSymbolAddress((void**)&sc,   g_sc);
    cudaGetSymbolAddress((void**)&relk, g_relk);
    cudaGetSymbolAddress((void**)&qb,   g_qb);
    cudaGetSymbolAddress((void**)&qkv,  g_qkv);
    cudaGetSymbolAddress((void**)&kv,   g_kv);
    cudaGetSymbolAddress((void**)&Sb,   g_S);
    cudaGetSymbolAddress((void**)&attn, g_attn);
    cudaGetSymbolAddress((void**)&x1,   g_x1);
    cudaGetSymbolAddress((void**)&x2,   g_x2);
    cudaGetSymbolAddress((void**)&x3,   g_x3);
    cudaGetSymbolAddress((void**)&tmp,  g_tmp);
    cudaGetSymbolAddress((void**)&ffh,  g_ffh);

    cudaFuncSetAttribute(relevance_tc,
                         cudaFuncAttributeMaxDynamicSharedMemorySize, REL_SMEM);

    // ---- relevant semantic -------------------------------------------------
    run_gemm(tgt, DD, mlp_w0,      2 * DD, nullptr, nullptr, fc, NTB,     DD, DD, 0);
    run_gemm(sem, DD, mlp_w0 + DD, 2 * DD, nullptr, nullptr, sc, BB * SS, DD, DD, 0);
    relevance_tc<<<NTB / 2, 256, REL_SMEM>>>(fc, sc, sem, mlp_b0, mlp_w1,
                                             mlp_b1, mlp_w2, relk);

    // ---- block 1: mha(tgt, sem_k, sem_k) + residual (no LN) ---------------
    run_gemm(tgt,  DD, pt_wqkv,           DD, pt_bqkv,      nullptr, qb, NTB, DD,     DD, 0);
    run_gemm(relk, DD, pt_wqkv + DD * DD, DD, pt_bqkv + DD, nullptr, kv, NTB, 2 * DD, DD, 0);
    attn_fused64<<<BB * HH, 256>>>(qb, DD, kv, 2 * DD, kv + DD, 2 * DD, attn);
    run_gemm(attn, DD, pt_wo, DD, pt_bo, tgt, x1, NTB, DD, DD, 0);

    // ---- block 2: self-attention + LN1 ------------------------------------
    run_gemm(x1, DD, sa_wqkv, DD, sa_bqkv, nullptr, qkv, NTB, 3 * DD, DD, 0);
    attn_fused64<<<BB * HH, 256>>>(qkv, 3 * DD, qkv + DD, 3 * DD, qkv + 2 * DD, 3 * DD, attn);
    run_gemm(attn, DD, sa_wo, DD, sa_bo, x1, tmp, NTB, DD, DD, 0);
    layernorm_kernel<<<NTB / 8, 256>>>(tmp, ln1_g, ln1_b, x2);

    // ---- block 3: cross-attention over memory + LN2 ------------------------
    run_gemm(x2,     DD, ca_wqkv,           DD, ca_bqkv,      nullptr, qb, NTB, DD,     DD, 0);
    run_gemm(memory, DD, ca_wqkv + DD * DD, DD, ca_bqkv + DD, nullptr, kv, NMB, 2 * DD, DD, 0);
    attn_scores_kernel<<<BB * HH, 256>>>(qb, DD, kv, 2 * DD, Sb, MM);
    softmax_rows_kernel<<<BB * HH * TT / 8, 256>>>(Sb, MM);
    attn_av_kernel<<<BB * HH, 256>>>(Sb, kv + DD, 2 * DD, attn, MM);
    run_gemm(attn, DD, ca_wo, DD, ca_bo, x2, tmp, NTB, DD, DD, 0);
    layernorm_kernel<<<NTB / 8, 256>>>(tmp, ln2_g, ln2_b, x3);

    // ---- FFN + LN3 ---------------------------------------------------------
    run_gemm(x3,  DD,  ffn_w1, DD,  ffn_b1, nullptr, ffh, NTB, FFD, DD,  1);
    run_gemm(ffh, FFD, ffn_w2, FFD, ffn_b2, x3,      tmp, NTB, DD,  FFD, 0);
    layernorm_kernel<<<NTB / 8, 256>>>(tmp, ln3_g, ln3_b, out);
}